// round 2
// baseline (speedup 1.0000x reference)
#include <cuda_runtime.h>

// Problem constants
#define BFULL 400
#define LQ 96            // query rows
#define CH 512           // channels
#define LC (LQ * CH)     // 49152 elements per batch

// Static device scratch (allocation-free per harness rules).
__device__ float g_xp80[80 * LC];
__device__ float g_cp80[80 * LC];
__device__ float g_xp16[16 * LC];
__device__ float g_cp16[16 * LC];
__device__ float g_A80 [80 * LC];
__device__ float g_A16 [16 * LC];

// ---------------------------------------------------------------------------
// 5-way mean pool from raw inputs -> level-80 pools (both streams).
// ---------------------------------------------------------------------------
__global__ void pool5_from_input(const float* __restrict__ x,
                                 const float* __restrict__ cr) {
    int t = blockIdx.x * blockDim.x + threadIdx.x;
    const int per = LC / 4;            // float4 per batch
    const int total = 80 * per;
    if (t >= total) return;
    int g = t / per;
    int m = t - g * per;
    const float4* xa = (const float4*)x;
    const float4* ca = (const float4*)cr;
    float4 sx = make_float4(0.f, 0.f, 0.f, 0.f);
    float4 sc = make_float4(0.f, 0.f, 0.f, 0.f);
#pragma unroll
    for (int j = 0; j < 5; j++) {
        float4 a = xa[(g * 5 + j) * per + m];
        float4 b = ca[(g * 5 + j) * per + m];
        sx.x += a.x; sx.y += a.y; sx.z += a.z; sx.w += a.w;
        sc.x += b.x; sc.y += b.y; sc.z += b.z; sc.w += b.w;
    }
    const float s = 0.2f;
    sx.x *= s; sx.y *= s; sx.z *= s; sx.w *= s;
    sc.x *= s; sc.y *= s; sc.z *= s; sc.w *= s;
    ((float4*)g_xp80)[g * per + m] = sx;
    ((float4*)g_cp80)[g * per + m] = sc;
}

// Level-16 pools from level-80 pools (mean of 5 => mean of 25 overall).
__global__ void pool5_level2() {
    int t = blockIdx.x * blockDim.x + threadIdx.x;
    const int per = LC / 4;
    const int total = 16 * per;
    if (t >= total) return;
    int g = t / per;
    int m = t - g * per;
    const float4* xa = (const float4*)g_xp80;
    const float4* ca = (const float4*)g_cp80;
    float4 sx = make_float4(0.f, 0.f, 0.f, 0.f);
    float4 sc = make_float4(0.f, 0.f, 0.f, 0.f);
#pragma unroll
    for (int j = 0; j < 5; j++) {
        float4 a = xa[(g * 5 + j) * per + m];
        float4 b = ca[(g * 5 + j) * per + m];
        sx.x += a.x; sx.y += a.y; sx.z += a.z; sx.w += a.w;
        sc.x += b.x; sc.y += b.y; sc.z += b.z; sc.w += b.w;
    }
    const float s = 0.2f;
    sx.x *= s; sx.y *= s; sx.z *= s; sx.w *= s;
    sc.x *= s; sc.y *= s; sc.z *= s; sc.w *= s;
    ((float4*)g_xp16)[g * per + m] = sx;
    ((float4*)g_cp16)[g * per + m] = sc;
}

// ---------------------------------------------------------------------------
// Attention for one batch per block: out = softmax(Q K^T / sqrt(C)) V with
// K == V (cross). 256 threads.
// If FUSED: writes (4/3)*A + (1/3)*(A16[b/25] + A80[b/5]) instead of A.
//
// Dynamic smem layout (floats):
//   sS   [96][97]  scores -> weights           (9312 floats)
//   sBuf [96*128]  phase1: Q[96][33]+K[96][33]; phase3: V chunk [96][128]
// Total = (9312 + 12288) * 4 = 86400 bytes.
// ---------------------------------------------------------------------------
template <bool FUSED>
__global__ void attn_kernel(const float* __restrict__ q,
                            const float* __restrict__ kv,
                            float* __restrict__ out,
                            const float* __restrict__ a16,
                            const float* __restrict__ a80) {
    extern __shared__ float smem[];
    float* sS   = smem;              // 96*97
    float* sBuf = smem + 96 * 97;

    const int b   = blockIdx.x;
    const int tid = threadIdx.x;
    const int tx  = tid & 15;
    const int ty  = tid >> 4;

    const float* qb = q  + (size_t)b * LC;
    const float* kb = kv + (size_t)b * LC;

    // ---- Phase 1: S = Q K^T -------------------------------------------------
    float acc[6][6];
#pragma unroll
    for (int i = 0; i < 6; i++)
#pragma unroll
        for (int j = 0; j < 6; j++) acc[i][j] = 0.f;

    float* sQ = sBuf;             // [96][33]
    float* sK = sBuf + 96 * 33;   // [96][33]

    const int lcol = tid & 31;
    const int lrow = tid >> 5;    // 0..7
    for (int kc = 0; kc < CH; kc += 32) {
        __syncthreads();
#pragma unroll
        for (int j = 0; j < 12; j++) {
            int row = lrow + j * 8;
            sQ[row * 33 + lcol] = qb[row * CH + kc + lcol];
            sK[row * 33 + lcol] = kb[row * CH + kc + lcol];
        }
        __syncthreads();
#pragma unroll
        for (int kk = 0; kk < 32; kk++) {
            float qf[6], kf[6];
#pragma unroll
            for (int i = 0; i < 6; i++) qf[i] = sQ[(ty + 16 * i) * 33 + kk];
#pragma unroll
            for (int j = 0; j < 6; j++) kf[j] = sK[(tx + 16 * j) * 33 + kk];
#pragma unroll
            for (int i = 0; i < 6; i++)
#pragma unroll
                for (int j = 0; j < 6; j++)
                    acc[i][j] = fmaf(qf[i], kf[j], acc[i][j]);
        }
    }
    const float scale = 0.04419417382415922f;  // 1/sqrt(512)
#pragma unroll
    for (int i = 0; i < 6; i++)
#pragma unroll
        for (int j = 0; j < 6; j++)
            sS[(ty + 16 * i) * 97 + (tx + 16 * j)] = acc[i][j] * scale;
    __syncthreads();

    // ---- Phase 2: row softmax ----------------------------------------------
    {
        const int w    = tid >> 5;
        const int lane = tid & 31;
        for (int l = w; l < 96; l += 8) {
            float* row = sS + l * 97;
            float v0 = row[lane], v1 = row[lane + 32], v2 = row[lane + 64];
            float m = fmaxf(v0, fmaxf(v1, v2));
#pragma unroll
            for (int o = 16; o > 0; o >>= 1)
                m = fmaxf(m, __shfl_xor_sync(0xffffffffu, m, o));
            float e0 = __expf(v0 - m), e1 = __expf(v1 - m), e2 = __expf(v2 - m);
            float s = e0 + e1 + e2;
#pragma unroll
            for (int o = 16; o > 0; o >>= 1)
                s += __shfl_xor_sync(0xffffffffu, s, o);
            float inv = 1.f / s;
            row[lane]      = e0 * inv;
            row[lane + 32] = e1 * inv;
            row[lane + 64] = e2 * inv;
        }
    }

    // ---- Phase 3: O = W V ---------------------------------------------------
    float* sV = sBuf;  // [96][128]
    const size_t obase = (size_t)b * LC;
    int b16 = 0, b80 = 0;
    if (FUSED) { b16 = b / 25; b80 = b / 5; }

    const int vcol = tid & 127;
    const int vrow = tid >> 7;  // 0..1
    for (int cc = 0; cc < CH; cc += 128) {
        __syncthreads();
#pragma unroll
        for (int j = 0; j < 48; j++) {
            int row = vrow + j * 2;
            sV[row * 128 + vcol] = kb[row * CH + cc + vcol];
        }
        __syncthreads();

        float acc2[6][8];
#pragma unroll
        for (int i = 0; i < 6; i++)
#pragma unroll
            for (int u = 0; u < 8; u++) acc2[i][u] = 0.f;

#pragma unroll 4
        for (int s = 0; s < 96; s++) {
            float wl[6];
#pragma unroll
            for (int i = 0; i < 6; i++) wl[i] = sS[(ty + 16 * i) * 97 + s];
            float4 va = *(const float4*)&sV[s * 128 + tx * 8];
            float4 vb = *(const float4*)&sV[s * 128 + tx * 8 + 4];
#pragma unroll
            for (int i = 0; i < 6; i++) {
                acc2[i][0] = fmaf(wl[i], va.x, acc2[i][0]);
                acc2[i][1] = fmaf(wl[i], va.y, acc2[i][1]);
                acc2[i][2] = fmaf(wl[i], va.z, acc2[i][2]);
                acc2[i][3] = fmaf(wl[i], va.w, acc2[i][3]);
                acc2[i][4] = fmaf(wl[i], vb.x, acc2[i][4]);
                acc2[i][5] = fmaf(wl[i], vb.y, acc2[i][5]);
                acc2[i][6] = fmaf(wl[i], vb.z, acc2[i][6]);
                acc2[i][7] = fmaf(wl[i], vb.w, acc2[i][7]);
            }
        }

#pragma unroll
        for (int i = 0; i < 6; i++) {
            int l = ty + 16 * i;
            size_t off = (size_t)l * CH + cc + tx * 8;
            float4 r0 = make_float4(acc2[i][0], acc2[i][1], acc2[i][2], acc2[i][3]);
            float4 r1 = make_float4(acc2[i][4], acc2[i][5], acc2[i][6], acc2[i][7]);
            if (FUSED) {
                const float c43 = 4.0f / 3.0f;
                const float c13 = 1.0f / 3.0f;
                const float4* p16 = (const float4*)(a16 + (size_t)b16 * LC + off);
                const float4* p80 = (const float4*)(a80 + (size_t)b80 * LC + off);
                float4 s0 = p16[0], s1 = p16[1];
                float4 t0 = p80[0], t1 = p80[1];
                r0.x = c43 * r0.x + c13 * (s0.x + t0.x);
                r0.y = c43 * r0.y + c13 * (s0.y + t0.y);
                r0.z = c43 * r0.z + c13 * (s0.z + t0.z);
                r0.w = c43 * r0.w + c13 * (s0.w + t0.w);
                r1.x = c43 * r1.x + c13 * (s1.x + t1.x);
                r1.y = c43 * r1.y + c13 * (s1.y + t1.y);
                r1.z = c43 * r1.z + c13 * (s1.z + t1.z);
                r1.w = c43 * r1.w + c13 * (s1.w + t1.w);
            }
            *(float4*)(out + obase + off)     = r0;
            *(float4*)(out + obase + off + 4) = r1;
        }
    }
}

// ---------------------------------------------------------------------------
extern "C" void kernel_launch(void* const* d_in, const int* in_sizes, int n_in,
                              void* d_out, int out_size) {
    const float* x     = (const float*)d_in[0];
    const float* cross = (const float*)d_in[1];
    float*       out   = (float*)d_out;

    const int SMEM_BYTES = (96 * 97 + 96 * 128) * 4;  // 86400

    // One-time host-side init (legal: host static, no device state dependency,
    // deterministic device work on every call).
    static float *p_xp80, *p_cp80, *p_xp16, *p_cp16, *p_A80, *p_A16;
    static bool init_done = false;
    if (!init_done) {
        cudaFuncSetAttribute(attn_kernel<false>,
                             cudaFuncAttributeMaxDynamicSharedMemorySize, SMEM_BYTES);
        cudaFuncSetAttribute(attn_kernel<true>,
                             cudaFuncAttributeMaxDynamicSharedMemorySize, SMEM_BYTES);
        void* p;
        cudaGetSymbolAddress(&p, g_xp80); p_xp80 = (float*)p;
        cudaGetSymbolAddress(&p, g_cp80); p_cp80 = (float*)p;
        cudaGetSymbolAddress(&p, g_xp16); p_xp16 = (float*)p;
        cudaGetSymbolAddress(&p, g_cp16); p_cp16 = (float*)p;
        cudaGetSymbolAddress(&p, g_A80);  p_A80  = (float*)p;
        cudaGetSymbolAddress(&p, g_A16);  p_A16  = (float*)p;
        init_done = true;
    }

    // 1) pool to 80
    {
        int total = 80 * (LC / 4);
        pool5_from_input<<<(total + 255) / 256, 256>>>(x, cross);
    }
    // 2) pool to 16
    {
        int total = 16 * (LC / 4);
        pool5_level2<<<(total + 255) / 256, 256>>>();
    }
    // 3) small attentions
    attn_kernel<false><<<16, 256, SMEM_BYTES>>>(
        p_xp16, p_cp16, p_A16, nullptr, nullptr);
    attn_kernel<false><<<80, 256, SMEM_BYTES>>>(
        p_xp80, p_cp80, p_A80, nullptr, nullptr);
    // 4) big attention, fused combine epilogue
    attn_kernel<true><<<400, 256, SMEM_BYTES>>>(
        x, cross, out, p_A16, p_A80);
}

// round 3
// speedup vs baseline: 1.5613x; 1.5613x over previous
#include <cuda_runtime.h>

#define LQ 96
#define CH 512
#define LC (LQ * CH)       // 49152
#define HR 48              // rows per half-CTA

// Static device scratch (allocation-free per harness rules).
__device__ float g_xp80[80 * LC];
__device__ float g_cp80[80 * LC];
__device__ float g_xp16[16 * LC];
__device__ float g_cp16[16 * LC];
__device__ float g_A80 [80 * LC];
__device__ float g_A16 [16 * LC];

// Packed fp32x2 ops (PTX-only; ptxas never auto-fuses these)
#define FMA2(d, a, b, c) \
    asm("fma.rn.f32x2 %0, %1, %2, %3;" : "=l"(d) : "l"(a), "l"(b), "l"(c))
#define PACK2(o, lo, hi) \
    asm("mov.b64 %0, {%1, %2};" : "=l"(o) : "f"(lo), "f"(hi))
#define UNPACK2(lo, hi, in) \
    asm("mov.b64 {%0, %1}, %2;" : "=f"(lo), "=f"(hi) : "l"(in))

// ---------------------------------------------------------------------------
// 5-way mean pools
// ---------------------------------------------------------------------------
__global__ void pool5_from_input(const float* __restrict__ x,
                                 const float* __restrict__ cr) {
    int t = blockIdx.x * blockDim.x + threadIdx.x;
    const int per = LC / 4;
    if (t >= 80 * per) return;
    int g = t / per;
    int m = t - g * per;
    const float4* xa = (const float4*)x;
    const float4* ca = (const float4*)cr;
    float4 sx = make_float4(0.f, 0.f, 0.f, 0.f);
    float4 sc = make_float4(0.f, 0.f, 0.f, 0.f);
#pragma unroll
    for (int j = 0; j < 5; j++) {
        float4 a = xa[(g * 5 + j) * per + m];
        float4 b = ca[(g * 5 + j) * per + m];
        sx.x += a.x; sx.y += a.y; sx.z += a.z; sx.w += a.w;
        sc.x += b.x; sc.y += b.y; sc.z += b.z; sc.w += b.w;
    }
    const float s = 0.2f;
    sx.x *= s; sx.y *= s; sx.z *= s; sx.w *= s;
    sc.x *= s; sc.y *= s; sc.z *= s; sc.w *= s;
    ((float4*)g_xp80)[g * per + m] = sx;
    ((float4*)g_cp80)[g * per + m] = sc;
}

__global__ void pool5_level2() {
    int t = blockIdx.x * blockDim.x + threadIdx.x;
    const int per = LC / 4;
    if (t >= 16 * per) return;
    int g = t / per;
    int m = t - g * per;
    const float4* xa = (const float4*)g_xp80;
    const float4* ca = (const float4*)g_cp80;
    float4 sx = make_float4(0.f, 0.f, 0.f, 0.f);
    float4 sc = make_float4(0.f, 0.f, 0.f, 0.f);
#pragma unroll
    for (int j = 0; j < 5; j++) {
        float4 a = xa[(g * 5 + j) * per + m];
        float4 b = ca[(g * 5 + j) * per + m];
        sx.x += a.x; sx.y += a.y; sx.z += a.z; sx.w += a.w;
        sc.x += b.x; sc.y += b.y; sc.z += b.z; sc.w += b.w;
    }
    const float s = 0.2f;
    sx.x *= s; sx.y *= s; sx.z *= s; sx.w *= s;
    sc.x *= s; sc.y *= s; sc.z *= s; sc.w *= s;
    ((float4*)g_xp16)[g * per + m] = sx;
    ((float4*)g_cp16)[g * per + m] = sc;
}

// ---------------------------------------------------------------------------
// Merged attention: all 496 batch-attentions in one launch.
// grid = 992: blockIdx -> (job, L-half). Job 0..15 -> A16, 16..95 -> A80,
// 96..495 -> raw A400 written straight into d_out.
// Each CTA: 48 query rows x full K/V of its batch. 256 threads.
//
// smem (floats): sS[48][97] (4656) + sBuf 12288 (phase1: sQ[48][33]+sKT[32][98];
//                phase3: sV[96][128]) = 67776 bytes -> 3 CTAs/SM.
// ---------------------------------------------------------------------------
__global__ __launch_bounds__(256, 3)
void attn_all(const float* __restrict__ x, const float* __restrict__ cross,
              float* out) {
    extern __shared__ float smem[];
    float* sS   = smem;            // 48*97
    float* sBuf = smem + 48 * 97;

    const int jid  = blockIdx.x >> 1;
    const int half = blockIdx.x & 1;
    const float *q, *kv;
    float* o;
    int b;
    if (jid < 16)      { q = g_xp16; kv = g_cp16; o = g_A16; b = jid; }
    else if (jid < 96) { q = g_xp80; kv = g_cp80; o = g_A80; b = jid - 16; }
    else               { q = x;      kv = cross;  o = out;   b = jid - 96; }

    const float* qb = q  + (size_t)b * LC + (size_t)half * HR * CH;
    const float* kb = kv + (size_t)b * LC;
    float*       ob = o  + (size_t)b * LC + (size_t)half * HR * CH;

    const int tid = threadIdx.x;
    const int tx  = tid >> 4;   // 0..15
    const int ty  = tid & 15;   // 0..15

    // ---- Phase 1: S[48][96] = Q_half K^T ------------------------------------
    float* sQ  = sBuf;              // [48][33]
    float* sKT = sBuf + 48 * 33;    // [32][98], transposed K chunk

    unsigned long long acc[3][3];
#pragma unroll
    for (int i = 0; i < 3; i++)
#pragma unroll
        for (int j = 0; j < 3; j++) acc[i][j] = 0ull;

    const int lc = tid & 31;
    const int lr = tid >> 5;    // 0..7
    for (int kc = 0; kc < CH; kc += 32) {
        __syncthreads();
#pragma unroll
        for (int j = 0; j < 6; j++) {
            int row = lr + 8 * j;
            sQ[row * 33 + lc] = qb[row * CH + kc + lc];
        }
#pragma unroll
        for (int j = 0; j < 12; j++) {
            int row = lr + 8 * j;
            sKT[lc * 98 + row] = kb[row * CH + kc + lc];
        }
        __syncthreads();
#pragma unroll 8
        for (int kk = 0; kk < 32; kk++) {
            unsigned long long qq[3], kp[3];
#pragma unroll
            for (int i = 0; i < 3; i++) {
                float qv = sQ[(ty + 16 * i) * 33 + kk];
                PACK2(qq[i], qv, qv);
            }
#pragma unroll
            for (int j = 0; j < 3; j++)
                kp[j] = *(const unsigned long long*)&sKT[kk * 98 + 2 * tx + 32 * j];
#pragma unroll
            for (int i = 0; i < 3; i++)
#pragma unroll
                for (int j = 0; j < 3; j++)
                    FMA2(acc[i][j], qq[i], kp[j], acc[i][j]);
        }
    }
    const float scale = 0.04419417382415922f;  // 1/sqrt(512)
#pragma unroll
    for (int i = 0; i < 3; i++)
#pragma unroll
        for (int j = 0; j < 3; j++) {
            float lo, hi;
            UNPACK2(lo, hi, acc[i][j]);
            int row = ty + 16 * i;
            int col = 2 * tx + 32 * j;
            sS[row * 97 + col]     = lo * scale;
            sS[row * 97 + col + 1] = hi * scale;
        }
    __syncthreads();

    // ---- Phase 2: row softmax (48 rows, 8 warps) ----------------------------
    {
        const int w    = tid >> 5;
        const int lane = tid & 31;
        for (int l = w; l < HR; l += 8) {
            float* row = sS + l * 97;
            float v0 = row[lane], v1 = row[lane + 32], v2 = row[lane + 64];
            float m = fmaxf(v0, fmaxf(v1, v2));
#pragma unroll
            for (int ofs = 16; ofs > 0; ofs >>= 1)
                m = fmaxf(m, __shfl_xor_sync(0xffffffffu, m, ofs));
            float e0 = __expf(v0 - m), e1 = __expf(v1 - m), e2 = __expf(v2 - m);
            float s = e0 + e1 + e2;
#pragma unroll
            for (int ofs = 16; ofs > 0; ofs >>= 1)
                s += __shfl_xor_sync(0xffffffffu, s, ofs);
            float inv = 1.f / s;
            row[lane]      = e0 * inv;
            row[lane + 32] = e1 * inv;
            row[lane + 64] = e2 * inv;
        }
    }

    // ---- Phase 3: O[48][512] = W V ------------------------------------------
    float* sV = sBuf;  // [96][128]
    const int c4 = tid & 31;
    const int vr = tid >> 5;
    for (int cc = 0; cc < CH; cc += 128) {
        __syncthreads();
#pragma unroll
        for (int j = 0; j < 12; j++) {
            int row = vr + 8 * j;
            *(float4*)&sV[row * 128 + c4 * 4] =
                *(const float4*)&kb[row * CH + cc + c4 * 4];
        }
        __syncthreads();

        unsigned long long acc2[3][4];
#pragma unroll
        for (int i = 0; i < 3; i++)
#pragma unroll
            for (int u = 0; u < 4; u++) acc2[i][u] = 0ull;

#pragma unroll 8
        for (int s = 0; s < 96; s++) {
            unsigned long long wl[3];
#pragma unroll
            for (int i = 0; i < 3; i++) {
                float wv = sS[(ty + 16 * i) * 97 + s];
                PACK2(wl[i], wv, wv);
            }
            // 8 cols per thread, warp-broadcast (2 distinct addrs/warp)
            ulonglong2 va = *(const ulonglong2*)&sV[s * 128 + tx * 8];
            ulonglong2 vb = *(const ulonglong2*)&sV[s * 128 + tx * 8 + 4];
#pragma unroll
            for (int i = 0; i < 3; i++) {
                FMA2(acc2[i][0], wl[i], va.x, acc2[i][0]);
                FMA2(acc2[i][1], wl[i], va.y, acc2[i][1]);
                FMA2(acc2[i][2], wl[i], vb.x, acc2[i][2]);
                FMA2(acc2[i][3], wl[i], vb.y, acc2[i][3]);
            }
        }

#pragma unroll
        for (int i = 0; i < 3; i++) {
            int row = ty + 16 * i;
            float r[8];
            UNPACK2(r[0], r[1], acc2[i][0]);
            UNPACK2(r[2], r[3], acc2[i][1]);
            UNPACK2(r[4], r[5], acc2[i][2]);
            UNPACK2(r[6], r[7], acc2[i][3]);
            float* dst = ob + (size_t)row * CH + cc + tx * 8;
            *(float4*)dst       = make_float4(r[0], r[1], r[2], r[3]);
            *(float4*)(dst + 4) = make_float4(r[4], r[5], r[6], r[7]);
        }
    }
}

// ---------------------------------------------------------------------------
// out = (4/3)*out + (1/3)*(A16[b/25] + A80[b/5])   (out holds raw A400)
// ---------------------------------------------------------------------------
__global__ void combine(float* __restrict__ out) {
    int t = blockIdx.x * blockDim.x + threadIdx.x;
    const int per = LC / 4;
    if (t >= 400 * per) return;
    int b = t / per;
    int m = t - b * per;
    int b16 = b / 25, b80 = b / 5;
    float4 a = ((float4*)out)[t];
    float4 s = ((const float4*)g_A16)[b16 * per + m];
    float4 u = ((const float4*)g_A80)[b80 * per + m];
    const float c43 = 4.0f / 3.0f, c13 = 1.0f / 3.0f;
    a.x = c43 * a.x + c13 * (s.x + u.x);
    a.y = c43 * a.y + c13 * (s.y + u.y);
    a.z = c43 * a.z + c13 * (s.z + u.z);
    a.w = c43 * a.w + c13 * (s.w + u.w);
    ((float4*)out)[t] = a;
}

// ---------------------------------------------------------------------------
extern "C" void kernel_launch(void* const* d_in, const int* in_sizes, int n_in,
                              void* d_out, int out_size) {
    const float* x     = (const float*)d_in[0];
    const float* cross = (const float*)d_in[1];
    float*       out   = (float*)d_out;

    const int SMEM_BYTES = (48 * 97 + 96 * 128) * 4;  // 67776

    static bool init_done = false;
    if (!init_done) {
        cudaFuncSetAttribute(attn_all,
                             cudaFuncAttributeMaxDynamicSharedMemorySize, SMEM_BYTES);
        init_done = true;
    }

    // 1) pools
    {
        int total = 80 * (LC / 4);
        pool5_from_input<<<(total + 255) / 256, 256>>>(x, cross);
    }
    {
        int total = 16 * (LC / 4);
        pool5_level2<<<(total + 255) / 256, 256>>>();
    }
    // 2) all 496 attentions, 2 CTAs per batch
    attn_all<<<992, 256, SMEM_BYTES>>>(x, cross, out);
    // 3) hierarchical combine
    {
        int total = 400 * (LC / 4);
        combine<<<(total + 255) / 256, 256>>>(out);
    }
}

// round 6
// speedup vs baseline: 2.1899x; 1.4026x over previous
#include <cuda_runtime.h>
#include <cuda_bf16.h>
#include <cstdint>

#define CH 512
#define LC (96 * 512)      // 49152

// Static device scratch (allocation-free per harness rules).
__device__ float g_xp80[80 * LC];
__device__ float g_cp80[80 * LC];
__device__ float g_xp16[16 * LC];
__device__ float g_cp16[16 * LC];
__device__ float g_A80 [80 * LC];
__device__ float g_A16 [16 * LC];

// ---------------------------------------------------------------------------
// helpers
// ---------------------------------------------------------------------------
__device__ __forceinline__ uint32_t smem_u32(const void* p) {
    uint32_t a;
    asm("{ .reg .u64 t; cvta.to.shared.u64 t, %1; cvt.u32.u64 %0, t; }"
        : "=r"(a) : "l"(p));
    return a;
}

#define LDSM_X4(r0, r1, r2, r3, addr) \
    asm volatile("ldmatrix.sync.aligned.m8n8.x4.shared.b16 {%0,%1,%2,%3}, [%4];" \
                 : "=r"(r0), "=r"(r1), "=r"(r2), "=r"(r3) : "r"(addr))
#define LDSM_X2(r0, r1, addr) \
    asm volatile("ldmatrix.sync.aligned.m8n8.x2.shared.b16 {%0,%1}, [%2];" \
                 : "=r"(r0), "=r"(r1) : "r"(addr))
#define LDSM_X2T(r0, r1, addr) \
    asm volatile("ldmatrix.sync.aligned.m8n8.x2.trans.shared.b16 {%0,%1}, [%2];" \
                 : "=r"(r0), "=r"(r1) : "r"(addr))

__device__ __forceinline__ void mma16816(float* d, uint32_t a0, uint32_t a1,
                                         uint32_t a2, uint32_t a3,
                                         uint32_t b0, uint32_t b1) {
    asm volatile("mma.sync.aligned.m16n8k16.row.col.f32.bf16.bf16.f32 "
                 "{%0,%1,%2,%3}, {%4,%5,%6,%7}, {%8,%9}, {%0,%1,%2,%3};"
                 : "+f"(d[0]), "+f"(d[1]), "+f"(d[2]), "+f"(d[3])
                 : "r"(a0), "r"(a1), "r"(a2), "r"(a3), "r"(b0), "r"(b1));
}

#define STS64V(addr, a, b) \
    asm volatile("st.shared.v2.b32 [%0], {%1,%2};" :: "r"(addr), "r"(a), "r"(b) : "memory")
#define STS32(addr, v) \
    asm volatile("st.shared.b32 [%0], %1;" :: "r"(addr), "r"(v) : "memory")

// bf16 hi/lo split
__device__ __forceinline__ void bsplit(float v, uint32_t& h, uint32_t& l) {
    __nv_bfloat16 hb = __float2bfloat16(v);
    float r = v - __bfloat162float(hb);
    __nv_bfloat16 lb = __float2bfloat16(r);
    h = (uint32_t)__bfloat16_as_ushort(hb);
    l = (uint32_t)__bfloat16_as_ushort(lb);
}

// ---------------------------------------------------------------------------
// 5-way mean pools (known good from R3)
// ---------------------------------------------------------------------------
__global__ void pool5_from_input(const float* __restrict__ x,
                                 const float* __restrict__ cr) {
    int t = blockIdx.x * blockDim.x + threadIdx.x;
    const int per = LC / 4;
    if (t >= 80 * per) return;
    int g = t / per, m = t - g * per;
    const float4* xa = (const float4*)x;
    const float4* ca = (const float4*)cr;
    float4 sx = make_float4(0, 0, 0, 0), sc = make_float4(0, 0, 0, 0);
#pragma unroll
    for (int j = 0; j < 5; j++) {
        float4 a = xa[(g * 5 + j) * per + m], b = ca[(g * 5 + j) * per + m];
        sx.x += a.x; sx.y += a.y; sx.z += a.z; sx.w += a.w;
        sc.x += b.x; sc.y += b.y; sc.z += b.z; sc.w += b.w;
    }
    const float s = 0.2f;
    sx.x *= s; sx.y *= s; sx.z *= s; sx.w *= s;
    sc.x *= s; sc.y *= s; sc.z *= s; sc.w *= s;
    ((float4*)g_xp80)[g * per + m] = sx;
    ((float4*)g_cp80)[g * per + m] = sc;
}

__global__ void pool5_level2() {
    int t = blockIdx.x * blockDim.x + threadIdx.x;
    const int per = LC / 4;
    if (t >= 16 * per) return;
    int g = t / per, m = t - g * per;
    const float4* xa = (const float4*)g_xp80;
    const float4* ca = (const float4*)g_cp80;
    float4 sx = make_float4(0, 0, 0, 0), sc = make_float4(0, 0, 0, 0);
#pragma unroll
    for (int j = 0; j < 5; j++) {
        float4 a = xa[(g * 5 + j) * per + m], b = ca[(g * 5 + j) * per + m];
        sx.x += a.x; sx.y += a.y; sx.z += a.z; sx.w += a.w;
        sc.x += b.x; sc.y += b.y; sc.z += b.z; sc.w += b.w;
    }
    const float s = 0.2f;
    sx.x *= s; sx.y *= s; sx.z *= s; sx.w *= s;
    sc.x *= s; sc.y *= s; sc.z *= s; sc.w *= s;
    ((float4*)g_xp16)[g * per + m] = sx;
    ((float4*)g_cp16)[g * per + m] = sc;
}

// ---------------------------------------------------------------------------
// Smem layout (bytes). Q/K/V tiles: 96 rows x 72 bf16 (144 B stride).
// W tiles: 96 rows x 104 bf16 (208 B stride). Phase overlap: W over Q, V over K.
// ---------------------------------------------------------------------------
#define QSTR 144
#define WSTR 208
#define SM_QHI 0u
#define SM_QLO 13824u
#define SM_KHI 27648u
#define SM_KLO 41472u      // phase-1 end: 55296
#define SM_WHI 0u
#define SM_WLO 19968u      // W end: 39936
#define SM_VHI 39936u
#define SM_VLO 53760u      // end: 67584
#define SMEM_TOTAL 67584

// ---------------------------------------------------------------------------
// Tensor-core (mma.sync bf16 hi/lo) attention. One CTA = one batch.
// 192 threads = 6 warps; warp w owns M rows [16w, 16w+16).
// ---------------------------------------------------------------------------
__global__ void __launch_bounds__(192, 3)
attn_mma(const float* __restrict__ x, const float* __restrict__ cross,
         float* out) {
    extern __shared__ char smem[];
    const uint32_t sb = smem_u32(smem);
    const int tid = threadIdx.x;
    const int w   = tid >> 5;
    const int l   = tid & 31;

    const int jid = blockIdx.x;
    const float *q, *kv;
    float* o;
    int b;
    if (jid < 16)      { q = g_xp16; kv = g_cp16; o = g_A16; b = jid; }
    else if (jid < 96) { q = g_xp80; kv = g_cp80; o = g_A80; b = jid - 16; }
    else               { q = x;      kv = cross;  o = out;   b = jid - 96; }
    const float* qb = q  + (size_t)b * LC;
    const float* kb = kv + (size_t)b * LC;
    float*       ob = o  + (size_t)b * LC;

    const int m0 = w * 16;
    // ldmatrix lane->address components
    const uint32_t arow = (uint32_t)(m0 + (l & 7) + ((l >> 3) & 1) * 8);
    const uint32_t aoffQ = arow * QSTR + ((l >> 4) & 1) * 16;
    const uint32_t aoffW = arow * WSTR + ((l >> 4) & 1) * 16;
    const int lb = l & 15;
    const uint32_t boffK = (uint32_t)((lb & 7) * QSTR + (lb >> 3) * 16);
    const uint32_t boffV = (uint32_t)(lb * QSTR);

    // ==== Phase 1: S = Q K^T, K-chunks of 32 channels ========================
    float acc[12][4];
#pragma unroll
    for (int n = 0; n < 12; n++)
#pragma unroll
        for (int u = 0; u < 4; u++) acc[n][u] = 0.f;

    for (int ck = 0; ck < 16; ck++) {
        const int kc = ck * 32;
        __syncthreads();   // prev iteration's mma reads done
#pragma unroll
        for (int i = 0; i < 4; i++) {
            int idx = tid + 192 * i;      // 0..767 float4s
            int row = idx >> 3, c4 = idx & 7;
            uint32_t a = (uint32_t)(row * QSTR + c4 * 8);
            float4 qv = *(const float4*)(qb + row * CH + kc + c4 * 4);
            uint32_t h0,l0,h1,l1,h2,l2,h3,l3;
            bsplit(qv.x,h0,l0); bsplit(qv.y,h1,l1); bsplit(qv.z,h2,l2); bsplit(qv.w,h3,l3);
            STS64V(sb + SM_QHI + a, h0 | (h1 << 16), h2 | (h3 << 16));
            STS64V(sb + SM_QLO + a, l0 | (l1 << 16), l2 | (l3 << 16));
            float4 kv4 = *(const float4*)(kb + row * CH + kc + c4 * 4);
            bsplit(kv4.x,h0,l0); bsplit(kv4.y,h1,l1); bsplit(kv4.z,h2,l2); bsplit(kv4.w,h3,l3);
            STS64V(sb + SM_KHI + a, h0 | (h1 << 16), h2 | (h3 << 16));
            STS64V(sb + SM_KLO + a, l0 | (l1 << 16), l2 | (l3 << 16));
        }
        __syncthreads();
#pragma unroll
        for (int ks = 0; ks < 2; ks++) {
            const uint32_t kB = (uint32_t)(ks * 32);  // 16 ch = 32 B
            uint32_t ah0,ah1,ah2,ah3, al0,al1,al2,al3;
            LDSM_X4(ah0,ah1,ah2,ah3, sb + SM_QHI + aoffQ + kB);
            LDSM_X4(al0,al1,al2,al3, sb + SM_QLO + aoffQ + kB);
#pragma unroll
            for (int n = 0; n < 12; n++) {
                uint32_t ba = sb + SM_KHI + (uint32_t)(n * 8 * QSTR) + boffK + kB;
                uint32_t bh0,bh1, bl0,bl1;
                LDSM_X2(bh0,bh1, ba);
                LDSM_X2(bl0,bl1, ba + (SM_KLO - SM_KHI));
                mma16816(acc[n], ah0,ah1,ah2,ah3, bh0,bh1);
                mma16816(acc[n], ah0,ah1,ah2,ah3, bl0,bl1);
                mma16816(acc[n], al0,al1,al2,al3, bh0,bh1);
            }
        }
    }
    __syncthreads();   // all mma done; Q/K region may be overwritten (by W)

    // ==== Phase 2: softmax in registers + W -> smem bf16 hi/lo ===============
    {
        const float scale = 0.04419417382415922f;  // 1/sqrt(512)
        const int g  = l >> 2;
        const int i4 = l & 3;
        const int r0 = m0 + g, r1 = r0 + 8;
        float mx0 = -3.4e38f, mx1 = -3.4e38f;
#pragma unroll
        for (int n = 0; n < 12; n++) {
#pragma unroll
            for (int u = 0; u < 4; u++) acc[n][u] *= scale;
            mx0 = fmaxf(mx0, fmaxf(acc[n][0], acc[n][1]));
            mx1 = fmaxf(mx1, fmaxf(acc[n][2], acc[n][3]));
        }
        mx0 = fmaxf(mx0, __shfl_xor_sync(0xffffffffu, mx0, 1));
        mx0 = fmaxf(mx0, __shfl_xor_sync(0xffffffffu, mx0, 2));
        mx1 = fmaxf(mx1, __shfl_xor_sync(0xffffffffu, mx1, 1));
        mx1 = fmaxf(mx1, __shfl_xor_sync(0xffffffffu, mx1, 2));
        float s0 = 0.f, s1 = 0.f;
#pragma unroll
        for (int n = 0; n < 12; n++) {
            acc[n][0] = __expf(acc[n][0] - mx0); s0 += acc[n][0];
            acc[n][1] = __expf(acc[n][1] - mx0); s0 += acc[n][1];
            acc[n][2] = __expf(acc[n][2] - mx1); s1 += acc[n][2];
            acc[n][3] = __expf(acc[n][3] - mx1); s1 += acc[n][3];
        }
        s0 += __shfl_xor_sync(0xffffffffu, s0, 1);
        s0 += __shfl_xor_sync(0xffffffffu, s0, 2);
        s1 += __shfl_xor_sync(0xffffffffu, s1, 1);
        s1 += __shfl_xor_sync(0xffffffffu, s1, 2);
        float i0 = 1.f / s0, i1 = 1.f / s1;
#pragma unroll
        for (int n = 0; n < 12; n++) {
            uint32_t cB = (uint32_t)(n * 16 + i4 * 4);  // col byte offset
            uint32_t h0,l0,h1,l1;
            bsplit(acc[n][0] * i0, h0, l0); bsplit(acc[n][1] * i0, h1, l1);
            STS32(sb + SM_WHI + (uint32_t)r0 * WSTR + cB, h0 | (h1 << 16));
            STS32(sb + SM_WLO + (uint32_t)r0 * WSTR + cB, l0 | (l1 << 16));
            bsplit(acc[n][2] * i1, h0, l0); bsplit(acc[n][3] * i1, h1, l1);
            STS32(sb + SM_WHI + (uint32_t)r1 * WSTR + cB, h0 | (h1 << 16));
            STS32(sb + SM_WLO + (uint32_t)r1 * WSTR + cB, l0 | (l1 << 16));
        }
    }

    // ==== Phase 3: O = W V, V chunks of 64 channels ==========================
    for (int ci = 0; ci < 8; ci++) {
        const int cc = ci * 64;
        __syncthreads();   // prev chunk mma reads done / W stores visible
#pragma unroll
        for (int i = 0; i < 8; i++) {
            int idx = tid + 192 * i;      // 0..1535 float4s
            int row = idx >> 4, c4 = idx & 15;
            uint32_t a = (uint32_t)(row * QSTR + c4 * 8);
            float4 vv = *(const float4*)(kb + row * CH + cc + c4 * 4);
            uint32_t h0,l0,h1,l1,h2,l2,h3,l3;
            bsplit(vv.x,h0,l0); bsplit(vv.y,h1,l1); bsplit(vv.z,h2,l2); bsplit(vv.w,h3,l3);
            STS64V(sb + SM_VHI + a, h0 | (h1 << 16), h2 | (h3 << 16));
            STS64V(sb + SM_VLO + a, l0 | (l1 << 16), l2 | (l3 << 16));
        }
        __syncthreads();

        float acc2[8][4];
#pragma unroll
        for (int n = 0; n < 8; n++)
#pragma unroll
            for (int u = 0; u < 4; u++) acc2[n][u] = 0.f;

#pragma unroll
        for (int ks = 0; ks < 6; ks++) {   // K dim = 96 key rows
            const uint32_t sB = (uint32_t)(ks * 32);          // A col byte
            const uint32_t vR = (uint32_t)(ks * 16 * QSTR);   // B row byte
            uint32_t ah0,ah1,ah2,ah3, al0,al1,al2,al3;
            LDSM_X4(ah0,ah1,ah2,ah3, sb + SM_WHI + aoffW + sB);
            LDSM_X4(al0,al1,al2,al3, sb + SM_WLO + aoffW + sB);
#pragma unroll
            for (int n = 0; n < 8; n++) {
                uint32_t ba = sb + SM_VHI + vR + boffV + (uint32_t)(n * 16);
                uint32_t bh0,bh1, bl0,bl1;
                LDSM_X2T(bh0,bh1, ba);
                LDSM_X2T(bl0,bl1, ba + (SM_VLO - SM_VHI));
                mma16816(acc2[n], ah0,ah1,ah2,ah3, bh0,bh1);
                mma16816(acc2[n], ah0,ah1,ah2,ah3, bl0,bl1);
                mma16816(acc2[n], al0,al1,al2,al3, bh0,bh1);
            }
        }
        {
            const int g  = l >> 2;
            const int i4 = l & 3;
            const int r0 = m0 + g, r1 = r0 + 8;
#pragma unroll
            for (int n = 0; n < 8; n++) {
                int col = cc + n * 8 + 2 * i4;
                *(float2*)(ob + (size_t)r0 * CH + col) = make_float2(acc2[n][0], acc2[n][1]);
                *(float2*)(ob + (size_t)r1 * CH + col) = make_float2(acc2[n][2], acc2[n][3]);
            }
        }
    }
}

// ---------------------------------------------------------------------------
// out = (4/3)*out + (1/3)*(A16[b/25] + A80[b/5])
// ---------------------------------------------------------------------------
__global__ void combine(float* __restrict__ out) {
    int t = blockIdx.x * blockDim.x + threadIdx.x;
    const int per = LC / 4;
    if (t >= 400 * per) return;
    int b = t / per, m = t - b * per;
    float4 a = ((float4*)out)[t];
    float4 s = ((const float4*)g_A16)[(b / 25) * per + m];
    float4 u = ((const float4*)g_A80)[(b / 5) * per + m];
    const float c43 = 4.0f / 3.0f, c13 = 1.0f / 3.0f;
    a.x = c43 * a.x + c13 * (s.x + u.x);
    a.y = c43 * a.y + c13 * (s.y + u.y);
    a.z = c43 * a.z + c13 * (s.z + u.z);
    a.w = c43 * a.w + c13 * (s.w + u.w);
    ((float4*)out)[t] = a;
}

// ---------------------------------------------------------------------------
extern "C" void kernel_launch(void* const* d_in, const int* in_sizes, int n_in,
                              void* d_out, int out_size) {
    const float* x     = (const float*)d_in[0];
    const float* cross = (const float*)d_in[1];
    float*       out   = (float*)d_out;

    static bool init_done = false;
    if (!init_done) {
        cudaFuncSetAttribute(attn_mma,
                             cudaFuncAttributeMaxDynamicSharedMemorySize, SMEM_TOTAL);
        init_done = true;
    }

    {
        int total = 80 * (LC / 4);
        pool5_from_input<<<(total + 255) / 256, 256>>>(x, cross);
    }
    {
        int total = 16 * (LC / 4);
        pool5_level2<<<(total + 255) / 256, 256>>>();
    }
    attn_mma<<<496, 192, SMEM_TOTAL>>>(x, cross, out);
    {
        int total = 400 * (LC / 4);
        combine<<<(total + 255) / 256, 256>>>(out);
    }
}

// round 7
// speedup vs baseline: 2.3095x; 1.0546x over previous
#include <cuda_runtime.h>
#include <cuda_bf16.h>
#include <cstdint>

#define CH 512
#define LC (96 * 512)      // 49152

// Static device scratch (allocation-free per harness rules).
__device__ float g_xp80[80 * LC];
__device__ float g_cp80[80 * LC];
__device__ float g_xp16[16 * LC];
__device__ float g_cp16[16 * LC];
__device__ float g_A80 [80 * LC];
__device__ float g_A16 [16 * LC];

// ---------------------------------------------------------------------------
// helpers
// ---------------------------------------------------------------------------
__device__ __forceinline__ uint32_t smem_u32(const void* p) {
    uint32_t a;
    asm("{ .reg .u64 t; cvta.to.shared.u64 t, %1; cvt.u32.u64 %0, t; }"
        : "=r"(a) : "l"(p));
    return a;
}

#define LDSM_X4(r0, r1, r2, r3, addr) \
    asm volatile("ldmatrix.sync.aligned.m8n8.x4.shared.b16 {%0,%1,%2,%3}, [%4];" \
                 : "=r"(r0), "=r"(r1), "=r"(r2), "=r"(r3) : "r"(addr))
#define LDSM_X4T(r0, r1, r2, r3, addr) \
    asm volatile("ldmatrix.sync.aligned.m8n8.x4.trans.shared.b16 {%0,%1,%2,%3}, [%4];" \
                 : "=r"(r0), "=r"(r1), "=r"(r2), "=r"(r3) : "r"(addr))

__device__ __forceinline__ void mma16816(float* d, uint32_t a0, uint32_t a1,
                                         uint32_t a2, uint32_t a3,
                                         uint32_t b0, uint32_t b1) {
    asm volatile("mma.sync.aligned.m16n8k16.row.col.f32.bf16.bf16.f32 "
                 "{%0,%1,%2,%3}, {%4,%5,%6,%7}, {%8,%9}, {%0,%1,%2,%3};"
                 : "+f"(d[0]), "+f"(d[1]), "+f"(d[2]), "+f"(d[3])
                 : "r"(a0), "r"(a1), "r"(a2), "r"(a3), "r"(b0), "r"(b1));
}

#define STS64V(addr, a, b) \
    asm volatile("st.shared.v2.b32 [%0], {%1,%2};" :: "r"(addr), "r"(a), "r"(b) : "memory")
#define STS32(addr, v) \
    asm volatile("st.shared.b32 [%0], %1;" :: "r"(addr), "r"(v) : "memory")

// bf16 hi/lo split
__device__ __forceinline__ void bsplit(float v, uint32_t& h, uint32_t& l) {
    __nv_bfloat16 hb = __float2bfloat16(v);
    float r = v - __bfloat162float(hb);
    __nv_bfloat16 lb = __float2bfloat16(r);
    h = (uint32_t)__bfloat16_as_ushort(hb);
    l = (uint32_t)__bfloat16_as_ushort(lb);
}

// ---------------------------------------------------------------------------
// 5-way mean pools
// ---------------------------------------------------------------------------
__global__ void pool5_from_input(const float* __restrict__ x,
                                 const float* __restrict__ cr) {
    int t = blockIdx.x * blockDim.x + threadIdx.x;
    const int per = LC / 4;
    if (t >= 80 * per) return;
    int g = t / per, m = t - g * per;
    const float4* xa = (const float4*)x;
    const float4* ca = (const float4*)cr;
    float4 sx = make_float4(0, 0, 0, 0), sc = make_float4(0, 0, 0, 0);
#pragma unroll
    for (int j = 0; j < 5; j++) {
        float4 a = xa[(g * 5 + j) * per + m], b = ca[(g * 5 + j) * per + m];
        sx.x += a.x; sx.y += a.y; sx.z += a.z; sx.w += a.w;
        sc.x += b.x; sc.y += b.y; sc.z += b.z; sc.w += b.w;
    }
    const float s = 0.2f;
    sx.x *= s; sx.y *= s; sx.z *= s; sx.w *= s;
    sc.x *= s; sc.y *= s; sc.z *= s; sc.w *= s;
    ((float4*)g_xp80)[g * per + m] = sx;
    ((float4*)g_cp80)[g * per + m] = sc;
}

__global__ void pool5_level2() {
    int t = blockIdx.x * blockDim.x + threadIdx.x;
    const int per = LC / 4;
    if (t >= 16 * per) return;
    int g = t / per, m = t - g * per;
    const float4* xa = (const float4*)g_xp80;
    const float4* ca = (const float4*)g_cp80;
    float4 sx = make_float4(0, 0, 0, 0), sc = make_float4(0, 0, 0, 0);
#pragma unroll
    for (int j = 0; j < 5; j++) {
        float4 a = xa[(g * 5 + j) * per + m], b = ca[(g * 5 + j) * per + m];
        sx.x += a.x; sx.y += a.y; sx.z += a.z; sx.w += a.w;
        sc.x += b.x; sc.y += b.y; sc.z += b.z; sc.w += b.w;
    }
    const float s = 0.2f;
    sx.x *= s; sx.y *= s; sx.z *= s; sx.w *= s;
    sc.x *= s; sc.y *= s; sc.z *= s; sc.w *= s;
    ((float4*)g_xp16)[g * per + m] = sx;
    ((float4*)g_cp16)[g * per + m] = sc;
}

// ---------------------------------------------------------------------------
// Smem layout (bytes). Q/K/V tiles: 96 rows x 144 B stride (64 ch bf16 + pad).
// W tiles: 96 rows x 208 B stride. Phase overlap: W over Q, V over K.
// ---------------------------------------------------------------------------
#define QSTR 144
#define WSTR 208
#define SM_QHI 0u
#define SM_QLO 13824u
#define SM_KHI 27648u
#define SM_KLO 41472u      // phase-1 end: 55296
#define SM_WHI 0u
#define SM_WLO 19968u      // W end: 39936
#define SM_VHI 39936u
#define SM_VLO 53760u      // end: 67584
#define SMEM_TOTAL 67584

// ---------------------------------------------------------------------------
// mma.sync bf16 hi/lo attention. One CTA = one job (jid = blockIdx.x + jbase).
// 192 threads = 6 warps; warp w owns M rows [16w, 16w+16).
// ---------------------------------------------------------------------------
__global__ void __launch_bounds__(192, 3)
attn_mma(const float* __restrict__ x, const float* __restrict__ cross,
         float* out, int jbase) {
    extern __shared__ char smem[];
    const uint32_t sb = smem_u32(smem);
    const int tid = threadIdx.x;
    const int w   = tid >> 5;
    const int l   = tid & 31;

    const int jid = blockIdx.x + jbase;
    const float *q, *kv;
    float* o;
    int b;
    if (jid < 16)      { q = g_xp16; kv = g_cp16; o = g_A16; b = jid; }
    else if (jid < 96) { q = g_xp80; kv = g_cp80; o = g_A80; b = jid - 16; }
    else               { q = x;      kv = cross;  o = out;   b = jid - 96; }
    const float* qb = q  + (size_t)b * LC;
    const float* kb = kv + (size_t)b * LC;
    float*       ob = o  + (size_t)b * LC;

    const int m0 = w * 16;
    // ldmatrix lane->address components (x4 pattern, shared by A and B)
    const uint32_t x4row = (uint32_t)((l & 7) + ((l >> 4) & 1) * 8);
    const uint32_t x4off = x4row * QSTR + ((l >> 3) & 1) * 16;     // K-major tiles
    const uint32_t aoffQ = (uint32_t)(m0 + (l & 7) + ((l >> 3) & 1) * 8) * QSTR
                         + ((l >> 4) & 1) * 16;
    const uint32_t aoffW = (uint32_t)(m0 + (l & 7) + ((l >> 3) & 1) * 8) * WSTR
                         + ((l >> 4) & 1) * 16;
    const uint32_t boffV4 = (uint32_t)((l & 15) * QSTR + ((l >> 4) & 1) * 16);

    // ==== Phase 1: S = Q K^T, K-chunks of 64 channels ========================
    float acc[12][4];
#pragma unroll
    for (int n = 0; n < 12; n++)
#pragma unroll
        for (int u = 0; u < 4; u++) acc[n][u] = 0.f;

    for (int ck = 0; ck < 8; ck++) {
        const int kc = ck * 64;
        __syncthreads();   // prev chunk's mma reads done
#pragma unroll
        for (int i = 0; i < 8; i++) {
            int idx = tid + 192 * i;      // 0..1535 float4 slots
            int row = idx >> 4, c4 = idx & 15;
            uint32_t a = (uint32_t)(row * QSTR + c4 * 8);
            float4 qv = *(const float4*)(qb + row * CH + kc + c4 * 4);
            uint32_t h0,l0,h1,l1,h2,l2,h3,l3;
            bsplit(qv.x,h0,l0); bsplit(qv.y,h1,l1); bsplit(qv.z,h2,l2); bsplit(qv.w,h3,l3);
            STS64V(sb + SM_QHI + a, h0 | (h1 << 16), h2 | (h3 << 16));
            STS64V(sb + SM_QLO + a, l0 | (l1 << 16), l2 | (l3 << 16));
            float4 kv4 = *(const float4*)(kb + row * CH + kc + c4 * 4);
            bsplit(kv4.x,h0,l0); bsplit(kv4.y,h1,l1); bsplit(kv4.z,h2,l2); bsplit(kv4.w,h3,l3);
            STS64V(sb + SM_KHI + a, h0 | (h1 << 16), h2 | (h3 << 16));
            STS64V(sb + SM_KLO + a, l0 | (l1 << 16), l2 | (l3 << 16));
        }
        __syncthreads();
#pragma unroll
        for (int ks = 0; ks < 4; ks++) {
            const uint32_t kB = (uint32_t)(ks * 32);  // 16 ch = 32 B
            uint32_t ah0,ah1,ah2,ah3, al0,al1,al2,al3;
            LDSM_X4(ah0,ah1,ah2,ah3, sb + SM_QHI + aoffQ + kB);
            LDSM_X4(al0,al1,al2,al3, sb + SM_QLO + aoffQ + kB);
#pragma unroll
            for (int n2 = 0; n2 < 6; n2++) {
                uint32_t ba = sb + SM_KHI + (uint32_t)(n2 * 16 * QSTR) + x4off + kB;
                uint32_t bh0,bh1,bh2,bh3, bl0,bl1,bl2,bl3;
                LDSM_X4(bh0,bh1,bh2,bh3, ba);
                LDSM_X4(bl0,bl1,bl2,bl3, ba + (SM_KLO - SM_KHI));
                mma16816(acc[2*n2],   ah0,ah1,ah2,ah3, bh0,bh1);
                mma16816(acc[2*n2],   ah0,ah1,ah2,ah3, bl0,bl1);
                mma16816(acc[2*n2],   al0,al1,al2,al3, bh0,bh1);
                mma16816(acc[2*n2+1], ah0,ah1,ah2,ah3, bh2,bh3);
                mma16816(acc[2*n2+1], ah0,ah1,ah2,ah3, bl2,bl3);
                mma16816(acc[2*n2+1], al0,al1,al2,al3, bh2,bh3);
            }
        }
    }
    __syncthreads();   // all mma done; Q/K region may be overwritten (by W)

    // ==== Phase 2: softmax in registers + W -> smem bf16 hi/lo ===============
    {
        const float scale = 0.04419417382415922f;  // 1/sqrt(512)
        const int g  = l >> 2;
        const int i4 = l & 3;
        const int r0 = m0 + g, r1 = r0 + 8;
        float mx0 = -3.4e38f, mx1 = -3.4e38f;
#pragma unroll
        for (int n = 0; n < 12; n++) {
#pragma unroll
            for (int u = 0; u < 4; u++) acc[n][u] *= scale;
            mx0 = fmaxf(mx0, fmaxf(acc[n][0], acc[n][1]));
            mx1 = fmaxf(mx1, fmaxf(acc[n][2], acc[n][3]));
        }
        mx0 = fmaxf(mx0, __shfl_xor_sync(0xffffffffu, mx0, 1));
        mx0 = fmaxf(mx0, __shfl_xor_sync(0xffffffffu, mx0, 2));
        mx1 = fmaxf(mx1, __shfl_xor_sync(0xffffffffu, mx1, 1));
        mx1 = fmaxf(mx1, __shfl_xor_sync(0xffffffffu, mx1, 2));
        float s0 = 0.f, s1 = 0.f;
#pragma unroll
        for (int n = 0; n < 12; n++) {
            acc[n][0] = __expf(acc[n][0] - mx0); s0 += acc[n][0];
            acc[n][1] = __expf(acc[n][1] - mx0); s0 += acc[n][1];
            acc[n][2] = __expf(acc[n][2] - mx1); s1 += acc[n][2];
            acc[n][3] = __expf(acc[n][3] - mx1); s1 += acc[n][3];
        }
        s0 += __shfl_xor_sync(0xffffffffu, s0, 1);
        s0 += __shfl_xor_sync(0xffffffffu, s0, 2);
        s1 += __shfl_xor_sync(0xffffffffu, s1, 1);
        s1 += __shfl_xor_sync(0xffffffffu, s1, 2);
        float i0 = 1.f / s0, i1 = 1.f / s1;
#pragma unroll
        for (int n = 0; n < 12; n++) {
            uint32_t cB = (uint32_t)(n * 16 + i4 * 4);  // col byte offset
            uint32_t h0,l0,h1,l1;
            bsplit(acc[n][0] * i0, h0, l0); bsplit(acc[n][1] * i0, h1, l1);
            STS32(sb + SM_WHI + (uint32_t)r0 * WSTR + cB, h0 | (h1 << 16));
            STS32(sb + SM_WLO + (uint32_t)r0 * WSTR + cB, l0 | (l1 << 16));
            bsplit(acc[n][2] * i1, h0, l0); bsplit(acc[n][3] * i1, h1, l1);
            STS32(sb + SM_WHI + (uint32_t)r1 * WSTR + cB, h0 | (h1 << 16));
            STS32(sb + SM_WLO + (uint32_t)r1 * WSTR + cB, l0 | (l1 << 16));
        }
    }

    // ==== Phase 3: O = W V, V chunks of 64 channels ==========================
    for (int ci = 0; ci < 8; ci++) {
        const int cc = ci * 64;
        __syncthreads();   // prev chunk mma reads done / W stores visible
#pragma unroll
        for (int i = 0; i < 8; i++) {
            int idx = tid + 192 * i;      // 0..1535 float4s
            int row = idx >> 4, c4 = idx & 15;
            uint32_t a = (uint32_t)(row * QSTR + c4 * 8);
            float4 vv = *(const float4*)(kb + row * CH + cc + c4 * 4);
            uint32_t h0,l0,h1,l1,h2,l2,h3,l3;
            bsplit(vv.x,h0,l0); bsplit(vv.y,h1,l1); bsplit(vv.z,h2,l2); bsplit(vv.w,h3,l3);
            STS64V(sb + SM_VHI + a, h0 | (h1 << 16), h2 | (h3 << 16));
            STS64V(sb + SM_VLO + a, l0 | (l1 << 16), l2 | (l3 << 16));
        }
        __syncthreads();

        float acc2[8][4];
#pragma unroll
        for (int n = 0; n < 8; n++)
#pragma unroll
            for (int u = 0; u < 4; u++) acc2[n][u] = 0.f;

#pragma unroll
        for (int ks = 0; ks < 6; ks++) {   // K dim = 96 key rows
            const uint32_t sB = (uint32_t)(ks * 32);          // A col byte
            const uint32_t vR = (uint32_t)(ks * 16 * QSTR);   // B row byte
            uint32_t ah0,ah1,ah2,ah3, al0,al1,al2,al3;
            LDSM_X4(ah0,ah1,ah2,ah3, sb + SM_WHI + aoffW + sB);
            LDSM_X4(al0,al1,al2,al3, sb + SM_WLO + aoffW + sB);
#pragma unroll
            for (int n2 = 0; n2 < 4; n2++) {
                uint32_t ba = sb + SM_VHI + vR + boffV4 + (uint32_t)(n2 * 32);
                uint32_t bh0,bh1,bh2,bh3, bl0,bl1,bl2,bl3;
                LDSM_X4T(bh0,bh1,bh2,bh3, ba);
                LDSM_X4T(bl0,bl1,bl2,bl3, ba + (SM_VLO - SM_VHI));
                mma16816(acc2[2*n2],   ah0,ah1,ah2,ah3, bh0,bh1);
                mma16816(acc2[2*n2],   ah0,ah1,ah2,ah3, bl0,bl1);
                mma16816(acc2[2*n2],   al0,al1,al2,al3, bh0,bh1);
                mma16816(acc2[2*n2+1], ah0,ah1,ah2,ah3, bh2,bh3);
                mma16816(acc2[2*n2+1], ah0,ah1,ah2,ah3, bl2,bl3);
                mma16816(acc2[2*n2+1], al0,al1,al2,al3, bh2,bh3);
            }
        }
        {
            const int g  = l >> 2;
            const int i4 = l & 3;
            const int r0 = m0 + g, r1 = r0 + 8;
#pragma unroll
            for (int n = 0; n < 8; n++) {
                int col = cc + n * 8 + 2 * i4;
                *(float2*)(ob + (size_t)r0 * CH + col) = make_float2(acc2[n][0], acc2[n][1]);
                *(float2*)(ob + (size_t)r1 * CH + col) = make_float2(acc2[n][2], acc2[n][3]);
            }
        }
    }
}

// ---------------------------------------------------------------------------
// out = (4/3)*out + (1/3)*(A16[b/25] + A80[b/5])
// ---------------------------------------------------------------------------
__global__ void combine(float* __restrict__ out) {
    int t = blockIdx.x * blockDim.x + threadIdx.x;
    const int per = LC / 4;
    if (t >= 400 * per) return;
    int b = t / per, m = t - b * per;
    float4 a = ((float4*)out)[t];
    float4 s = ((const float4*)g_A16)[(b / 25) * per + m];
    float4 u = ((const float4*)g_A80)[(b / 5) * per + m];
    const float c43 = 4.0f / 3.0f, c13 = 1.0f / 3.0f;
    a.x = c43 * a.x + c13 * (s.x + u.x);
    a.y = c43 * a.y + c13 * (s.y + u.y);
    a.z = c43 * a.z + c13 * (s.z + u.z);
    a.w = c43 * a.w + c13 * (s.w + u.w);
    ((float4*)out)[t] = a;
}

// ---------------------------------------------------------------------------
extern "C" void kernel_launch(void* const* d_in, const int* in_sizes, int n_in,
                              void* d_out, int out_size) {
    const float* x     = (const float*)d_in[0];
    const float* cross = (const float*)d_in[1];
    float*       out   = (float*)d_out;

    static bool init_done = false;
    static cudaStream_t s2;
    static cudaEvent_t e0, e1;
    if (!init_done) {
        cudaFuncSetAttribute(attn_mma,
                             cudaFuncAttributeMaxDynamicSharedMemorySize, SMEM_TOTAL);
        cudaStreamCreateWithFlags(&s2, cudaStreamNonBlocking);
        cudaEventCreateWithFlags(&e0, cudaEventDisableTiming);
        cudaEventCreateWithFlags(&e1, cudaEventDisableTiming);
        init_done = true;
    }

    // Fork: side stream runs pools + 96 pooled-attention jobs; main stream
    // runs the 400 raw-attention jobs concurrently (no pool dependency).
    cudaEventRecord(e0, 0);
    cudaStreamWaitEvent(s2, e0, 0);

    {
        int total = 80 * (LC / 4);
        pool5_from_input<<<(total + 255) / 256, 256, 0, s2>>>(x, cross);
    }
    {
        int total = 16 * (LC / 4);
        pool5_level2<<<(total + 255) / 256, 256, 0, s2>>>();
    }
    attn_mma<<<96, 192, SMEM_TOTAL, s2>>>(x, cross, out, 0);     // jobs 0..95
    attn_mma<<<400, 192, SMEM_TOTAL>>>(x, cross, out, 96);       // jobs 96..495

    // Join, then combine.
    cudaEventRecord(e1, s2);
    cudaStreamWaitEvent(0, e1, 0);
    {
        int total = 400 * (LC / 4);
        combine<<<(total + 255) / 256, 256>>>(out);
    }
}

// round 8
// speedup vs baseline: 2.5313x; 1.0960x over previous
#include <cuda_runtime.h>
#include <cuda_bf16.h>
#include <cstdint>

#define CH 512
#define LC (96 * 512)      // 49152

// Static device scratch (allocation-free per harness rules).
__device__ float g_xp80[80 * LC];
__device__ float g_cp80[80 * LC];
__device__ float g_xp16[16 * LC];
__device__ float g_cp16[16 * LC];
__device__ float g_A80 [80 * LC];
__device__ float g_A16 [16 * LC];

// ---------------------------------------------------------------------------
// helpers
// ---------------------------------------------------------------------------
__device__ __forceinline__ uint32_t smem_u32(const void* p) {
    uint32_t a;
    asm("{ .reg .u64 t; cvta.to.shared.u64 t, %1; cvt.u32.u64 %0, t; }"
        : "=r"(a) : "l"(p));
    return a;
}

#define LDSM_X4(r0, r1, r2, r3, addr) \
    asm volatile("ldmatrix.sync.aligned.m8n8.x4.shared.b16 {%0,%1,%2,%3}, [%4];" \
                 : "=r"(r0), "=r"(r1), "=r"(r2), "=r"(r3) : "r"(addr))
#define LDSM_X4T(r0, r1, r2, r3, addr) \
    asm volatile("ldmatrix.sync.aligned.m8n8.x4.trans.shared.b16 {%0,%1,%2,%3}, [%4];" \
                 : "=r"(r0), "=r"(r1), "=r"(r2), "=r"(r3) : "r"(addr))

__device__ __forceinline__ void mma16816(float* d, uint32_t a0, uint32_t a1,
                                         uint32_t a2, uint32_t a3,
                                         uint32_t b0, uint32_t b1) {
    asm volatile("mma.sync.aligned.m16n8k16.row.col.f32.bf16.bf16.f32 "
                 "{%0,%1,%2,%3}, {%4,%5,%6,%7}, {%8,%9}, {%0,%1,%2,%3};"
                 : "+f"(d[0]), "+f"(d[1]), "+f"(d[2]), "+f"(d[3])
                 : "r"(a0), "r"(a1), "r"(a2), "r"(a3), "r"(b0), "r"(b1));
}

#define STS64V(addr, a, b) \
    asm volatile("st.shared.v2.b32 [%0], {%1,%2};" :: "r"(addr), "r"(a), "r"(b) : "memory")
#define STS32(addr, v) \
    asm volatile("st.shared.b32 [%0], %1;" :: "r"(addr), "r"(v) : "memory")

// bf16 hi/lo split
__device__ __forceinline__ void bsplit(float v, uint32_t& h, uint32_t& l) {
    __nv_bfloat16 hb = __float2bfloat16(v);
    float r = v - __bfloat162float(hb);
    __nv_bfloat16 lb = __float2bfloat16(r);
    h = (uint32_t)__bfloat16_as_ushort(hb);
    l = (uint32_t)__bfloat16_as_ushort(lb);
}

// ---------------------------------------------------------------------------
// Fused pools: level-80 (mean of 5) and level-16 (mean of 25, straight from
// raw input; re-reads hit L2 hot from the level-80 pass).
// ---------------------------------------------------------------------------
__global__ void pools_all(const float* __restrict__ x,
                          const float* __restrict__ cr) {
    const int per = LC / 4;
    int t = blockIdx.x * blockDim.x + threadIdx.x;
    if (t < 80 * per) {
        int g = t / per, m = t - g * per;
        const float4* xa = (const float4*)x;
        const float4* ca = (const float4*)cr;
        float4 sx = make_float4(0, 0, 0, 0), sc = make_float4(0, 0, 0, 0);
#pragma unroll
        for (int j = 0; j < 5; j++) {
            float4 a = xa[(g * 5 + j) * per + m], b = ca[(g * 5 + j) * per + m];
            sx.x += a.x; sx.y += a.y; sx.z += a.z; sx.w += a.w;
            sc.x += b.x; sc.y += b.y; sc.z += b.z; sc.w += b.w;
        }
        const float s = 0.2f;
        sx.x *= s; sx.y *= s; sx.z *= s; sx.w *= s;
        sc.x *= s; sc.y *= s; sc.z *= s; sc.w *= s;
        ((float4*)g_xp80)[g * per + m] = sx;
        ((float4*)g_cp80)[g * per + m] = sc;
    } else if (t < 96 * per) {
        int u = t - 80 * per;
        int g = u / per, m = u - g * per;
        const float4* xa = (const float4*)x;
        const float4* ca = (const float4*)cr;
        float4 sx = make_float4(0, 0, 0, 0), sc = make_float4(0, 0, 0, 0);
#pragma unroll
        for (int j = 0; j < 25; j++) {
            float4 a = xa[(g * 25 + j) * per + m], b = ca[(g * 25 + j) * per + m];
            sx.x += a.x; sx.y += a.y; sx.z += a.z; sx.w += a.w;
            sc.x += b.x; sc.y += b.y; sc.z += b.z; sc.w += b.w;
        }
        const float s = 0.04f;
        sx.x *= s; sx.y *= s; sx.z *= s; sx.w *= s;
        sc.x *= s; sc.y *= s; sc.z *= s; sc.w *= s;
        ((float4*)g_xp16)[g * per + m] = sx;
        ((float4*)g_cp16)[g * per + m] = sc;
    }
}

// ---------------------------------------------------------------------------
// Smem layout (bytes).
// Phase 1: QHI/QLO/KHI/KLO, 96 rows x 144 B stride (64 ch bf16), 4 x 13824.
// Phase 2/3: WHI/WLO 96 x 208 B; VHI/VLO 96 x 80 B (32-ch chunks).
// Max = 55296; total 55424 -> 4 CTAs/SM.
// ---------------------------------------------------------------------------
#define QSTR 144
#define WSTR 208
#define VSTR 80
#define SM_QHI 0u
#define SM_QLO 13824u
#define SM_KHI 27648u
#define SM_KLO 41472u      // phase-1 end: 55296
#define SM_WHI 0u
#define SM_WLO 19968u      // W end: 39936
#define SM_VHI 39936u
#define SM_VLO 47616u      // end: 55296
#define SMEM_TOTAL 55424

// ---------------------------------------------------------------------------
// mma.sync bf16 hi/lo attention. One CTA = one job. 192 threads = 6 warps;
// warp w owns M rows [16w, 16w+16). 4 CTAs/SM target (<=85 regs).
// ---------------------------------------------------------------------------
__global__ void __launch_bounds__(192, 4)
attn_mma(const float* __restrict__ x, const float* __restrict__ cross,
         float* out) {
    extern __shared__ char smem[];
    const uint32_t sb = smem_u32(smem);
    const int tid = threadIdx.x;
    const int w   = tid >> 5;
    const int l   = tid & 31;

    const int jid = blockIdx.x;
    const float *q, *kv;
    float* o;
    int b;
    if (jid < 16)      { q = g_xp16; kv = g_cp16; o = g_A16; b = jid; }
    else if (jid < 96) { q = g_xp80; kv = g_cp80; o = g_A80; b = jid - 16; }
    else               { q = x;      kv = cross;  o = out;   b = jid - 96; }
    const float* qb = q  + (size_t)b * LC;
    const float* kb = kv + (size_t)b * LC;
    float*       ob = o  + (size_t)b * LC;

    const int m0 = w * 16;
    // ldmatrix lane->address components
    const uint32_t x4off = (uint32_t)((l & 7) + ((l >> 4) & 1) * 8) * QSTR
                         + ((l >> 3) & 1) * 16;                        // K tiles
    const uint32_t aoffQ = (uint32_t)(m0 + (l & 7) + ((l >> 3) & 1) * 8) * QSTR
                         + ((l >> 4) & 1) * 16;
    const uint32_t aoffW = (uint32_t)(m0 + (l & 7) + ((l >> 3) & 1) * 8) * WSTR
                         + ((l >> 4) & 1) * 16;
    const uint32_t boffV4 = (uint32_t)((l & 15) * VSTR + ((l >> 4) & 1) * 16);

    // ==== Phase 1: S = Q K^T, K-chunks of 64 channels ========================
    float acc[12][4];
#pragma unroll
    for (int n = 0; n < 12; n++)
#pragma unroll
        for (int u = 0; u < 4; u++) acc[n][u] = 0.f;

    for (int ck = 0; ck < 8; ck++) {
        const int kc = ck * 64;
        __syncthreads();   // prev chunk's mma reads done
#pragma unroll
        for (int i = 0; i < 8; i++) {
            int idx = tid + 192 * i;      // 0..1535 float4 slots
            int row = idx >> 4, c4 = idx & 15;
            uint32_t a = (uint32_t)(row * QSTR + c4 * 8);
            float4 qv = *(const float4*)(qb + row * CH + kc + c4 * 4);
            uint32_t h0,l0,h1,l1,h2,l2,h3,l3;
            bsplit(qv.x,h0,l0); bsplit(qv.y,h1,l1); bsplit(qv.z,h2,l2); bsplit(qv.w,h3,l3);
            STS64V(sb + SM_QHI + a, h0 | (h1 << 16), h2 | (h3 << 16));
            STS64V(sb + SM_QLO + a, l0 | (l1 << 16), l2 | (l3 << 16));
            float4 kv4 = *(const float4*)(kb + row * CH + kc + c4 * 4);
            bsplit(kv4.x,h0,l0); bsplit(kv4.y,h1,l1); bsplit(kv4.z,h2,l2); bsplit(kv4.w,h3,l3);
            STS64V(sb + SM_KHI + a, h0 | (h1 << 16), h2 | (h3 << 16));
            STS64V(sb + SM_KLO + a, l0 | (l1 << 16), l2 | (l3 << 16));
        }
        __syncthreads();
#pragma unroll
        for (int ks = 0; ks < 4; ks++) {
            const uint32_t kB = (uint32_t)(ks * 32);  // 16 ch = 32 B
            uint32_t ah0,ah1,ah2,ah3, al0,al1,al2,al3;
            LDSM_X4(ah0,ah1,ah2,ah3, sb + SM_QHI + aoffQ + kB);
            LDSM_X4(al0,al1,al2,al3, sb + SM_QLO + aoffQ + kB);
#pragma unroll
            for (int n2 = 0; n2 < 6; n2++) {
                uint32_t ba = sb + SM_KHI + (uint32_t)(n2 * 16 * QSTR) + x4off + kB;
                uint32_t bh0,bh1,bh2,bh3, bl0,bl1,bl2,bl3;
                LDSM_X4(bh0,bh1,bh2,bh3, ba);
                LDSM_X4(bl0,bl1,bl2,bl3, ba + (SM_KLO - SM_KHI));
                mma16816(acc[2*n2],   ah0,ah1,ah2,ah3, bh0,bh1);
                mma16816(acc[2*n2],   ah0,ah1,ah2,ah3, bl0,bl1);
                mma16816(acc[2*n2],   al0,al1,al2,al3, bh0,bh1);
                mma16816(acc[2*n2+1], ah0,ah1,ah2,ah3, bh2,bh3);
                mma16816(acc[2*n2+1], ah0,ah1,ah2,ah3, bl2,bl3);
                mma16816(acc[2*n2+1], al0,al1,al2,al3, bh2,bh3);
            }
        }
    }
    __syncthreads();   // all mma done; Q/K region may be overwritten (by W)

    // ==== Phase 2: softmax in registers + W -> smem bf16 hi/lo ===============
    {
        const float scale = 0.04419417382415922f;  // 1/sqrt(512)
        const int g  = l >> 2;
        const int i4 = l & 3;
        const int r0 = m0 + g, r1 = r0 + 8;
        float mx0 = -3.4e38f, mx1 = -3.4e38f;
#pragma unroll
        for (int n = 0; n < 12; n++) {
#pragma unroll
            for (int u = 0; u < 4; u++) acc[n][u] *= scale;
            mx0 = fmaxf(mx0, fmaxf(acc[n][0], acc[n][1]));
            mx1 = fmaxf(mx1, fmaxf(acc[n][2], acc[n][3]));
        }
        mx0 = fmaxf(mx0, __shfl_xor_sync(0xffffffffu, mx0, 1));
        mx0 = fmaxf(mx0, __shfl_xor_sync(0xffffffffu, mx0, 2));
        mx1 = fmaxf(mx1, __shfl_xor_sync(0xffffffffu, mx1, 1));
        mx1 = fmaxf(mx1, __shfl_xor_sync(0xffffffffu, mx1, 2));
        float s0 = 0.f, s1 = 0.f;
#pragma unroll
        for (int n = 0; n < 12; n++) {
            acc[n][0] = __expf(acc[n][0] - mx0); s0 += acc[n][0];
            acc[n][1] = __expf(acc[n][1] - mx0); s0 += acc[n][1];
            acc[n][2] = __expf(acc[n][2] - mx1); s1 += acc[n][2];
            acc[n][3] = __expf(acc[n][3] - mx1); s1 += acc[n][3];
        }
        s0 += __shfl_xor_sync(0xffffffffu, s0, 1);
        s0 += __shfl_xor_sync(0xffffffffu, s0, 2);
        s1 += __shfl_xor_sync(0xffffffffu, s1, 1);
        s1 += __shfl_xor_sync(0xffffffffu, s1, 2);
        float i0 = 1.f / s0, i1 = 1.f / s1;
#pragma unroll
        for (int n = 0; n < 12; n++) {
            uint32_t cB = (uint32_t)(n * 16 + i4 * 4);  // col byte offset
            uint32_t h0,l0,h1,l1;
            bsplit(acc[n][0] * i0, h0, l0); bsplit(acc[n][1] * i0, h1, l1);
            STS32(sb + SM_WHI + (uint32_t)r0 * WSTR + cB, h0 | (h1 << 16));
            STS32(sb + SM_WLO + (uint32_t)r0 * WSTR + cB, l0 | (l1 << 16));
            bsplit(acc[n][2] * i1, h0, l0); bsplit(acc[n][3] * i1, h1, l1);
            STS32(sb + SM_WHI + (uint32_t)r1 * WSTR + cB, h0 | (h1 << 16));
            STS32(sb + SM_WLO + (uint32_t)r1 * WSTR + cB, l0 | (l1 << 16));
        }
    }

    // ==== Phase 3: O = W V, V chunks of 32 channels ==========================
    for (int ci = 0; ci < 16; ci++) {
        const int cc = ci * 32;
        __syncthreads();   // prev chunk mma reads done / W stores visible
#pragma unroll
        for (int i = 0; i < 4; i++) {
            int idx = tid + 192 * i;      // 0..767 float4s
            int row = idx >> 3, c4 = idx & 7;
            uint32_t a = (uint32_t)(row * VSTR + c4 * 8);
            float4 vv = *(const float4*)(kb + row * CH + cc + c4 * 4);
            uint32_t h0,l0,h1,l1,h2,l2,h3,l3;
            bsplit(vv.x,h0,l0); bsplit(vv.y,h1,l1); bsplit(vv.z,h2,l2); bsplit(vv.w,h3,l3);
            STS64V(sb + SM_VHI + a, h0 | (h1 << 16), h2 | (h3 << 16));
            STS64V(sb + SM_VLO + a, l0 | (l1 << 16), l2 | (l3 << 16));
        }
        __syncthreads();

        float acc2[4][4];
#pragma unroll
        for (int n = 0; n < 4; n++)
#pragma unroll
            for (int u = 0; u < 4; u++) acc2[n][u] = 0.f;

#pragma unroll
        for (int ks = 0; ks < 6; ks++) {   // K dim = 96 key rows
            const uint32_t sB = (uint32_t)(ks * 32);          // A col byte
            const uint32_t vR = (uint32_t)(ks * 16 * VSTR);   // B row byte
            uint32_t ah0,ah1,ah2,ah3, al0,al1,al2,al3;
            LDSM_X4(ah0,ah1,ah2,ah3, sb + SM_WHI + aoffW + sB);
            LDSM_X4(al0,al1,al2,al3, sb + SM_WLO + aoffW + sB);
#pragma unroll
            for (int n2 = 0; n2 < 2; n2++) {
                uint32_t ba = sb + SM_VHI + vR + boffV4 + (uint32_t)(n2 * 32);
                uint32_t bh0,bh1,bh2,bh3, bl0,bl1,bl2,bl3;
                LDSM_X4T(bh0,bh1,bh2,bh3, ba);
                LDSM_X4T(bl0,bl1,bl2,bl3, ba + (SM_VLO - SM_VHI));
                mma16816(acc2[2*n2],   ah0,ah1,ah2,ah3, bh0,bh1);
                mma16816(acc2[2*n2],   ah0,ah1,ah2,ah3, bl0,bl1);
                mma16816(acc2[2*n2],   al0,al1,al2,al3, bh0,bh1);
                mma16816(acc2[2*n2+1], ah0,ah1,ah2,ah3, bh2,bh3);
                mma16816(acc2[2*n2+1], ah0,ah1,ah2,ah3, bl2,bl3);
                mma16816(acc2[2*n2+1], al0,al1,al2,al3, bh2,bh3);
            }
        }
        {
            const int g  = l >> 2;
            const int i4 = l & 3;
            const int r0 = m0 + g, r1 = r0 + 8;
#pragma unroll
            for (int n = 0; n < 4; n++) {
                int col = cc + n * 8 + 2 * i4;
                *(float2*)(ob + (size_t)r0 * CH + col) = make_float2(acc2[n][0], acc2[n][1]);
                *(float2*)(ob + (size_t)r1 * CH + col) = make_float2(acc2[n][2], acc2[n][3]);
            }
        }
    }
}

// ---------------------------------------------------------------------------
// out = (4/3)*out + (1/3)*(A16[b/25] + A80[b/5])
// ---------------------------------------------------------------------------
__global__ void combine(float* __restrict__ out) {
    int t = blockIdx.x * blockDim.x + threadIdx.x;
    const int per = LC / 4;
    if (t >= 400 * per) return;
    int b = t / per, m = t - b * per;
    float4 a = ((float4*)out)[t];
    float4 s = ((const float4*)g_A16)[(b / 25) * per + m];
    float4 u = ((const float4*)g_A80)[(b / 5) * per + m];
    const float c43 = 4.0f / 3.0f, c13 = 1.0f / 3.0f;
    a.x = c43 * a.x + c13 * (s.x + u.x);
    a.y = c43 * a.y + c13 * (s.y + u.y);
    a.z = c43 * a.z + c13 * (s.z + u.z);
    a.w = c43 * a.w + c13 * (s.w + u.w);
    ((float4*)out)[t] = a;
}

// ---------------------------------------------------------------------------
extern "C" void kernel_launch(void* const* d_in, const int* in_sizes, int n_in,
                              void* d_out, int out_size) {
    const float* x     = (const float*)d_in[0];
    const float* cross = (const float*)d_in[1];
    float*       out   = (float*)d_out;

    static bool init_done = false;
    if (!init_done) {
        cudaFuncSetAttribute(attn_mma,
                             cudaFuncAttributeMaxDynamicSharedMemorySize, SMEM_TOTAL);
        init_done = true;
    }

    {
        int total = 96 * (LC / 4);
        pools_all<<<(total + 255) / 256, 256>>>(x, cross);
    }
    attn_mma<<<496, 192, SMEM_TOTAL>>>(x, cross, out);
    {
        int total = 400 * (LC / 4);
        combine<<<(total + 255) / 256, 256>>>(out);
    }
}

// round 9
// speedup vs baseline: 2.7853x; 1.1004x over previous
#include <cuda_runtime.h>
#include <cuda_bf16.h>
#include <cstdint>

#define CH 512
#define LC (96 * 512)      // 49152

// Static device scratch (allocation-free per harness rules).
__device__ float g_xp80[80 * LC];
__device__ float g_cp80[80 * LC];
__device__ float g_xp16[16 * LC];
__device__ float g_cp16[16 * LC];
__device__ float g_A80 [80 * LC];
__device__ float g_A16 [16 * LC];

// ---------------------------------------------------------------------------
// helpers
// ---------------------------------------------------------------------------
__device__ __forceinline__ uint32_t smem_u32(const void* p) {
    uint32_t a;
    asm("{ .reg .u64 t; cvta.to.shared.u64 t, %1; cvt.u32.u64 %0, t; }"
        : "=r"(a) : "l"(p));
    return a;
}

#define LDSM_X4(r0, r1, r2, r3, addr) \
    asm volatile("ldmatrix.sync.aligned.m8n8.x4.shared.b16 {%0,%1,%2,%3}, [%4];" \
                 : "=r"(r0), "=r"(r1), "=r"(r2), "=r"(r3) : "r"(addr))
#define LDSM_X4T(r0, r1, r2, r3, addr) \
    asm volatile("ldmatrix.sync.aligned.m8n8.x4.trans.shared.b16 {%0,%1,%2,%3}, [%4];" \
                 : "=r"(r0), "=r"(r1), "=r"(r2), "=r"(r3) : "r"(addr))

__device__ __forceinline__ void mma16816(float* d, uint32_t a0, uint32_t a1,
                                         uint32_t a2, uint32_t a3,
                                         uint32_t b0, uint32_t b1) {
    asm volatile("mma.sync.aligned.m16n8k16.row.col.f32.bf16.bf16.f32 "
                 "{%0,%1,%2,%3}, {%4,%5,%6,%7}, {%8,%9}, {%0,%1,%2,%3};"
                 : "+f"(d[0]), "+f"(d[1]), "+f"(d[2]), "+f"(d[3])
                 : "r"(a0), "r"(a1), "r"(a2), "r"(a3), "r"(b0), "r"(b1));
}

#define STS64V(addr, a, b) \
    asm volatile("st.shared.v2.b32 [%0], {%1,%2};" :: "r"(addr), "r"(a), "r"(b) : "memory")

// bf16 hi/lo split (scalar)
__device__ __forceinline__ void bsplit(float v, uint32_t& h, uint32_t& l) {
    __nv_bfloat16 hb = __float2bfloat16(v);
    float r = v - __bfloat162float(hb);
    __nv_bfloat16 lb = __float2bfloat16(r);
    h = (uint32_t)__bfloat16_as_ushort(hb);
    l = (uint32_t)__bfloat16_as_ushort(lb);
}
// pack two floats to bf16x2 hi/lo pair (v0 -> low 16 bits)
__device__ __forceinline__ void bpack2(float v0, float v1,
                                       uint32_t& hi, uint32_t& lo) {
    uint32_t h0, l0, h1, l1;
    bsplit(v0, h0, l0); bsplit(v1, h1, l1);
    hi = h0 | (h1 << 16);
    lo = l0 | (l1 << 16);
}

// ---------------------------------------------------------------------------
// 5-way mean pools (two-stage; level-16 derived from level-80 buffer)
// ---------------------------------------------------------------------------
__global__ void pool5_from_input(const float* __restrict__ x,
                                 const float* __restrict__ cr) {
    int t = blockIdx.x * blockDim.x + threadIdx.x;
    const int per = LC / 4;
    if (t >= 80 * per) return;
    int g = t / per, m = t - g * per;
    const float4* xa = (const float4*)x;
    const float4* ca = (const float4*)cr;
    float4 sx = make_float4(0, 0, 0, 0), sc = make_float4(0, 0, 0, 0);
#pragma unroll
    for (int j = 0; j < 5; j++) {
        float4 a = xa[(g * 5 + j) * per + m], b = ca[(g * 5 + j) * per + m];
        sx.x += a.x; sx.y += a.y; sx.z += a.z; sx.w += a.w;
        sc.x += b.x; sc.y += b.y; sc.z += b.z; sc.w += b.w;
    }
    const float s = 0.2f;
    sx.x *= s; sx.y *= s; sx.z *= s; sx.w *= s;
    sc.x *= s; sc.y *= s; sc.z *= s; sc.w *= s;
    ((float4*)g_xp80)[g * per + m] = sx;
    ((float4*)g_cp80)[g * per + m] = sc;
}

__global__ void pool5_level2() {
    int t = blockIdx.x * blockDim.x + threadIdx.x;
    const int per = LC / 4;
    if (t >= 16 * per) return;
    int g = t / per, m = t - g * per;
    const float4* xa = (const float4*)g_xp80;
    const float4* ca = (const float4*)g_cp80;
    float4 sx = make_float4(0, 0, 0, 0), sc = make_float4(0, 0, 0, 0);
#pragma unroll
    for (int j = 0; j < 5; j++) {
        float4 a = xa[(g * 5 + j) * per + m], b = ca[(g * 5 + j) * per + m];
        sx.x += a.x; sx.y += a.y; sx.z += a.z; sx.w += a.w;
        sc.x += b.x; sc.y += b.y; sc.z += b.z; sc.w += b.w;
    }
    const float s = 0.2f;
    sx.x *= s; sx.y *= s; sx.z *= s; sx.w *= s;
    sc.x *= s; sc.y *= s; sc.z *= s; sc.w *= s;
    ((float4*)g_xp16)[g * per + m] = sx;
    ((float4*)g_cp16)[g * per + m] = sc;
}

// ---------------------------------------------------------------------------
// Smem layout (bytes).
// Phase 1: QHI/QLO/KHI/KLO, 96 rows x 144 B stride (64 ch bf16), 4 x 13824.
// Phase 3: VHI/VLO 96 x 144 B (64-ch chunks), overlapping the phase-1 area.
// Total 55296 -> 4 CTAs/SM.
// ---------------------------------------------------------------------------
#define QSTR 144
#define SM_QHI 0u
#define SM_QLO 13824u
#define SM_KHI 27648u
#define SM_KLO 41472u      // end: 55296
#define SM_VHI 0u
#define SM_VLO 13824u      // end: 27648
#define SMEM_TOTAL 55296

// ---------------------------------------------------------------------------
// mma.sync bf16 hi/lo attention; softmax weights stay in registers as
// A-fragments for GEMM2 (no W smem round-trip).
// One CTA = one job. 192 threads = 6 warps; warp w owns M rows [16w,16w+16).
// ---------------------------------------------------------------------------
__global__ void __launch_bounds__(192, 4)
attn_mma(const float* __restrict__ x, const float* __restrict__ cross,
         float* out) {
    extern __shared__ char smem[];
    const uint32_t sb = smem_u32(smem);
    const int tid = threadIdx.x;
    const int w   = tid >> 5;
    const int l   = tid & 31;

    const int jid = blockIdx.x;
    const float *q, *kv;
    float* o;
    int b;
    if (jid < 16)      { q = g_xp16; kv = g_cp16; o = g_A16; b = jid; }
    else if (jid < 96) { q = g_xp80; kv = g_cp80; o = g_A80; b = jid - 16; }
    else               { q = x;      kv = cross;  o = out;   b = jid - 96; }
    const float* qb = q  + (size_t)b * LC;
    const float* kb = kv + (size_t)b * LC;
    float*       ob = o  + (size_t)b * LC;

    const int m0 = w * 16;
    // ldmatrix lane->address components
    const uint32_t x4off = (uint32_t)((l & 7) + ((l >> 4) & 1) * 8) * QSTR
                         + ((l >> 3) & 1) * 16;                        // K tiles
    const uint32_t aoffQ = (uint32_t)(m0 + (l & 7) + ((l >> 3) & 1) * 8) * QSTR
                         + ((l >> 4) & 1) * 16;
    const uint32_t boffV4 = (uint32_t)((l & 15) * QSTR + ((l >> 4) & 1) * 16);

    // ==== Phase 1: S = Q K^T, K-chunks of 64 channels ========================
    float acc[12][4];
#pragma unroll
    for (int n = 0; n < 12; n++)
#pragma unroll
        for (int u = 0; u < 4; u++) acc[n][u] = 0.f;

    for (int ck = 0; ck < 8; ck++) {
        const int kc = ck * 64;
        __syncthreads();   // prev chunk's mma reads done
#pragma unroll
        for (int i = 0; i < 8; i++) {
            int idx = tid + 192 * i;      // 0..1535 float4 slots
            int row = idx >> 4, c4 = idx & 15;
            uint32_t a = (uint32_t)(row * QSTR + c4 * 8);
            float4 qv = *(const float4*)(qb + row * CH + kc + c4 * 4);
            uint32_t p0h, p0l, p1h, p1l;
            bpack2(qv.x, qv.y, p0h, p0l);
            bpack2(qv.z, qv.w, p1h, p1l);
            STS64V(sb + SM_QHI + a, p0h, p1h);
            STS64V(sb + SM_QLO + a, p0l, p1l);
            float4 kv4 = *(const float4*)(kb + row * CH + kc + c4 * 4);
            bpack2(kv4.x, kv4.y, p0h, p0l);
            bpack2(kv4.z, kv4.w, p1h, p1l);
            STS64V(sb + SM_KHI + a, p0h, p1h);
            STS64V(sb + SM_KLO + a, p0l, p1l);
        }
        __syncthreads();
#pragma unroll
        for (int ks = 0; ks < 4; ks++) {
            const uint32_t kB = (uint32_t)(ks * 32);  // 16 ch = 32 B
            uint32_t ah0,ah1,ah2,ah3, al0,al1,al2,al3;
            LDSM_X4(ah0,ah1,ah2,ah3, sb + SM_QHI + aoffQ + kB);
            LDSM_X4(al0,al1,al2,al3, sb + SM_QLO + aoffQ + kB);
#pragma unroll
            for (int n2 = 0; n2 < 6; n2++) {
                uint32_t ba = sb + SM_KHI + (uint32_t)(n2 * 16 * QSTR) + x4off + kB;
                uint32_t bh0,bh1,bh2,bh3, bl0,bl1,bl2,bl3;
                LDSM_X4(bh0,bh1,bh2,bh3, ba);
                LDSM_X4(bl0,bl1,bl2,bl3, ba + (SM_KLO - SM_KHI));
                mma16816(acc[2*n2],   ah0,ah1,ah2,ah3, bh0,bh1);
                mma16816(acc[2*n2],   ah0,ah1,ah2,ah3, bl0,bl1);
                mma16816(acc[2*n2],   al0,al1,al2,al3, bh0,bh1);
                mma16816(acc[2*n2+1], ah0,ah1,ah2,ah3, bh2,bh3);
                mma16816(acc[2*n2+1], ah0,ah1,ah2,ah3, bl2,bl3);
                mma16816(acc[2*n2+1], al0,al1,al2,al3, bh2,bh3);
            }
        }
    }
    __syncthreads();   // all mma done; smem free for V

    // ==== Phase 2: softmax in registers -> A-fragments in registers ==========
    uint32_t whi[24], wlo[24];
    {
        const float scale = 0.04419417382415922f;  // 1/sqrt(512)
        float mx0 = -3.4e38f, mx1 = -3.4e38f;
#pragma unroll
        for (int n = 0; n < 12; n++) {
#pragma unroll
            for (int u = 0; u < 4; u++) acc[n][u] *= scale;
            mx0 = fmaxf(mx0, fmaxf(acc[n][0], acc[n][1]));
            mx1 = fmaxf(mx1, fmaxf(acc[n][2], acc[n][3]));
        }
        mx0 = fmaxf(mx0, __shfl_xor_sync(0xffffffffu, mx0, 1));
        mx0 = fmaxf(mx0, __shfl_xor_sync(0xffffffffu, mx0, 2));
        mx1 = fmaxf(mx1, __shfl_xor_sync(0xffffffffu, mx1, 1));
        mx1 = fmaxf(mx1, __shfl_xor_sync(0xffffffffu, mx1, 2));
        float s0 = 0.f, s1 = 0.f;
#pragma unroll
        for (int n = 0; n < 12; n++) {
            acc[n][0] = __expf(acc[n][0] - mx0); s0 += acc[n][0];
            acc[n][1] = __expf(acc[n][1] - mx0); s0 += acc[n][1];
            acc[n][2] = __expf(acc[n][2] - mx1); s1 += acc[n][2];
            acc[n][3] = __expf(acc[n][3] - mx1); s1 += acc[n][3];
        }
        s0 += __shfl_xor_sync(0xffffffffu, s0, 1);
        s0 += __shfl_xor_sync(0xffffffffu, s0, 2);
        s1 += __shfl_xor_sync(0xffffffffu, s1, 1);
        s1 += __shfl_xor_sync(0xffffffffu, s1, 2);
        float i0 = 1.f / s0, i1 = 1.f / s1;
        // Convert to A-fragments: for k-step ks, regs {a0,a1,a2,a3} =
        // {pack(acc[2ks][0..1]), pack(acc[2ks][2..3]),
        //  pack(acc[2ks+1][0..1]), pack(acc[2ks+1][2..3])}
#pragma unroll
        for (int ks = 0; ks < 6; ks++) {
            bpack2(acc[2*ks][0] * i0,   acc[2*ks][1] * i0,   whi[4*ks+0], wlo[4*ks+0]);
            bpack2(acc[2*ks][2] * i1,   acc[2*ks][3] * i1,   whi[4*ks+1], wlo[4*ks+1]);
            bpack2(acc[2*ks+1][0] * i0, acc[2*ks+1][1] * i0, whi[4*ks+2], wlo[4*ks+2]);
            bpack2(acc[2*ks+1][2] * i1, acc[2*ks+1][3] * i1, whi[4*ks+3], wlo[4*ks+3]);
        }
    }

    // ==== Phase 3: O = W V, V chunks of 64 channels, 32-col half-passes ======
    for (int ci = 0; ci < 8; ci++) {
        const int cc = ci * 64;
        __syncthreads();   // prev chunk mma reads done
#pragma unroll
        for (int i = 0; i < 8; i++) {
            int idx = tid + 192 * i;      // 0..1535 float4s
            int row = idx >> 4, c4 = idx & 15;
            uint32_t a = (uint32_t)(row * QSTR + c4 * 8);
            float4 vv = *(const float4*)(kb + row * CH + cc + c4 * 4);
            uint32_t p0h, p0l, p1h, p1l;
            bpack2(vv.x, vv.y, p0h, p0l);
            bpack2(vv.z, vv.w, p1h, p1l);
            STS64V(sb + SM_VHI + a, p0h, p1h);
            STS64V(sb + SM_VLO + a, p0l, p1l);
        }
        __syncthreads();

#pragma unroll
        for (int h = 0; h < 2; h++) {
            float acc2[4][4];
#pragma unroll
            for (int n = 0; n < 4; n++)
#pragma unroll
                for (int u = 0; u < 4; u++) acc2[n][u] = 0.f;

#pragma unroll
            for (int ks = 0; ks < 6; ks++) {
                const uint32_t vR = (uint32_t)(ks * 16 * QSTR);
#pragma unroll
                for (int n2 = 0; n2 < 2; n2++) {
                    uint32_t ba = sb + SM_VHI + vR + boffV4
                                + (uint32_t)(h * 64 + n2 * 32);
                    uint32_t bh0,bh1,bh2,bh3, bl0,bl1,bl2,bl3;
                    LDSM_X4T(bh0,bh1,bh2,bh3, ba);
                    LDSM_X4T(bl0,bl1,bl2,bl3, ba + (SM_VLO - SM_VHI));
                    mma16816(acc2[2*n2],   whi[4*ks],whi[4*ks+1],whi[4*ks+2],whi[4*ks+3], bh0,bh1);
                    mma16816(acc2[2*n2],   whi[4*ks],whi[4*ks+1],whi[4*ks+2],whi[4*ks+3], bl0,bl1);
                    mma16816(acc2[2*n2],   wlo[4*ks],wlo[4*ks+1],wlo[4*ks+2],wlo[4*ks+3], bh0,bh1);
                    mma16816(acc2[2*n2+1], whi[4*ks],whi[4*ks+1],whi[4*ks+2],whi[4*ks+3], bh2,bh3);
                    mma16816(acc2[2*n2+1], whi[4*ks],whi[4*ks+1],whi[4*ks+2],whi[4*ks+3], bl2,bl3);
                    mma16816(acc2[2*n2+1], wlo[4*ks],wlo[4*ks+1],wlo[4*ks+2],wlo[4*ks+3], bh2,bh3);
                }
            }
            {
                const int g  = l >> 2;
                const int i4 = l & 3;
                const int r0 = m0 + g, r1 = r0 + 8;
#pragma unroll
                for (int n = 0; n < 4; n++) {
                    int col = cc + h * 32 + n * 8 + 2 * i4;
                    *(float2*)(ob + (size_t)r0 * CH + col) = make_float2(acc2[n][0], acc2[n][1]);
                    *(float2*)(ob + (size_t)r1 * CH + col) = make_float2(acc2[n][2], acc2[n][3]);
                }
            }
        }
    }
}

// ---------------------------------------------------------------------------
// out = (4/3)*out + (1/3)*(A16[b/25] + A80[b/5])
// ---------------------------------------------------------------------------
__global__ void combine(float* __restrict__ out) {
    int t = blockIdx.x * blockDim.x + threadIdx.x;
    const int per = LC / 4;
    if (t >= 400 * per) return;
    int b = t / per, m = t - b * per;
    float4 a = ((float4*)out)[t];
    float4 s = ((const float4*)g_A16)[(b / 25) * per + m];
    float4 u = ((const float4*)g_A80)[(b / 5) * per + m];
    const float c43 = 4.0f / 3.0f, c13 = 1.0f / 3.0f;
    a.x = c43 * a.x + c13 * (s.x + u.x);
    a.y = c43 * a.y + c13 * (s.y + u.y);
    a.z = c43 * a.z + c13 * (s.z + u.z);
    a.w = c43 * a.w + c13 * (s.w + u.w);
    ((float4*)out)[t] = a;
}

// ---------------------------------------------------------------------------
extern "C" void kernel_launch(void* const* d_in, const int* in_sizes, int n_in,
                              void* d_out, int out_size) {
    const float* x     = (const float*)d_in[0];
    const float* cross = (const float*)d_in[1];
    float*       out   = (float*)d_out;

    static bool init_done = false;
    if (!init_done) {
        cudaFuncSetAttribute(attn_mma,
                             cudaFuncAttributeMaxDynamicSharedMemorySize, SMEM_TOTAL);
        init_done = true;
    }

    {
        int total = 80 * (LC / 4);
        pool5_from_input<<<(total + 255) / 256, 256>>>(x, cross);
    }
    {
        int total = 16 * (LC / 4);
        pool5_level2<<<(total + 255) / 256, 256>>>();
    }
    attn_mma<<<496, 192, SMEM_TOTAL>>>(x, cross, out);
    {
        int total = 400 * (LC / 4);
        combine<<<(total + 255) / 256, 256>>>(out);
    }
}